// round 12
// baseline (speedup 1.0000x reference)
#include <cuda_runtime.h>
#include <cstdint>

// ---------------------------------------------------------------------------
// Problem constants
// ---------------------------------------------------------------------------
#define B_   2
#define N_   65536
#define M_   16384
#define C1_  128
#define C2_  256
#define H1_  256
#define H2_  128
#define NT_  512
#define EPS_ 1e-5f
#define GDIM  64
#define CELLS (GDIM * GDIM * GDIM)    // 262144 cells per batch, h = 0.125

// ---------------------------------------------------------------------------
// Scratch (device globals -- no allocation allowed)
// ---------------------------------------------------------------------------
__device__ int    g_idx[B_ * N_];
__device__ float  g_P[(size_t)B_ * M_ * H1_];      // TRANSPOSED: [b][m][o]
__device__ float  g_h[(size_t)B_ * H1_ * N_];
__device__ float  g_part1[(size_t)B_ * H1_ * NT_ * 2];
__device__ float  g_part2[(size_t)B_ * H2_ * NT_ * 2];
__device__ float  g_scale1[H1_], g_bias1[H1_];
__device__ float  g_scale2[H2_], g_bias2[H2_];

// grid-NN scratch
__device__ int    g_kcnt[B_ * CELLS], g_kstart[B_ * CELLS], g_kcur[B_ * CELLS];
__device__ int    g_qcnt[B_ * CELLS], g_qstart[B_ * CELLS], g_qcur[B_ * CELLS];
__device__ int    g_kcell[B_ * M_],  g_qcell[B_ * N_];
__device__ __align__(16) float4 g_ksort[B_ * M_];
__device__ __align__(16) float4 g_qsort[B_ * N_];
__device__ int    g_korig[B_ * M_], g_qorig[B_ * N_];

// ---------------------------------------------------------------------------
// helpers
// ---------------------------------------------------------------------------
__device__ __forceinline__ uint32_t cvt_tf32(float f) {
    uint32_t u;
    asm("cvt.rna.tf32.f32 %0, %1;" : "=r"(u) : "f"(f));
    return u;
}
__device__ __forceinline__ void mma_tf32(float* c, const uint32_t* a,
                                         uint32_t b0, uint32_t b1) {
    asm volatile(
        "mma.sync.aligned.m16n8k8.row.col.f32.tf32.tf32.f32 "
        "{%0,%1,%2,%3}, {%4,%5,%6,%7}, {%8,%9}, {%0,%1,%2,%3};\n"
        : "+f"(c[0]), "+f"(c[1]), "+f"(c[2]), "+f"(c[3])
        : "r"(a[0]), "r"(a[1]), "r"(a[2]), "r"(a[3]), "r"(b0), "r"(b1));
}
__device__ __forceinline__ int cellof(float v) {
    int c = __float2int_rd((v + 4.0f) * 8.0f);
    return min(GDIM - 1, max(0, c));
}

// ---------------------------------------------------------------------------
// Binning: zero counters -> histogram -> scan -> scatter
// ---------------------------------------------------------------------------
__global__ void zero_kernel() {
    int i = blockIdx.x * 256 + threadIdx.x;
    if (i < B_ * CELLS) { g_kcnt[i] = 0; g_qcnt[i] = 0; }
}

__global__ void hist_kernel(const float* __restrict__ unknown,
                            const float* __restrict__ known) {
    int j = blockIdx.x * 256 + threadIdx.x;
    if (j < B_ * M_) {
        float x = known[3 * j], y = known[3 * j + 1], z = known[3 * j + 2];
        int cell = (cellof(z) * GDIM + cellof(y)) * GDIM + cellof(x);
        g_kcell[j] = cell;
        atomicAdd(&g_kcnt[(j / M_) * CELLS + cell], 1);
    } else {
        int q = j - B_ * M_;
        if (q < B_ * N_) {
            float x = unknown[3 * q], y = unknown[3 * q + 1], z = unknown[3 * q + 2];
            int cell = (cellof(z) * GDIM + cellof(y)) * GDIM + cellof(x);
            g_qcell[q] = cell;
            atomicAdd(&g_qcnt[(q / N_) * CELLS + cell], 1);
        }
    }
}

// one block per (array, batch): 0,1 = knowns b0/b1; 2,3 = queries b0/b1.
// 1024 threads x 256 cells/thread, int4 traffic, block exclusive scan.
__global__ void __launch_bounds__(1024) scan_kernel() {
    const int w = blockIdx.x;
    int* cnt;  int* start;  int* cur;
    if (w < 2) { cnt = g_kcnt + w * CELLS; start = g_kstart + w * CELLS; cur = g_kcur + w * CELLS; }
    else { int b = w - 2; cnt = g_qcnt + b * CELLS; start = g_qstart + b * CELLS; cur = g_qcur + b * CELLS; }
    const int t = threadIdx.x;
    const int base = t * (CELLS / 1024);          // 256 cells per thread
    int s = 0;
    for (int i = 0; i < CELLS / 1024; i += 4) {
        int4 v = *(const int4*)&cnt[base + i];
        s += v.x + v.y + v.z + v.w;
    }
    const int lane = t & 31, wid = t >> 5;
    int v = s;
#pragma unroll
    for (int off = 1; off < 32; off <<= 1) {
        int n = __shfl_up_sync(0xffffffffu, v, off);
        if (lane >= off) v += n;
    }
    __shared__ int ws[32];
    if (lane == 31) ws[wid] = v;
    __syncthreads();
    if (wid == 0) {
        int x = ws[lane];
#pragma unroll
        for (int off = 1; off < 32; off <<= 1) {
            int n = __shfl_up_sync(0xffffffffu, x, off);
            if (lane >= off) x += n;
        }
        ws[lane] = x;
    }
    __syncthreads();
    int run = v - s + (wid > 0 ? ws[wid - 1] : 0);   // exclusive prefix
    for (int i = 0; i < CELLS / 1024; i += 4) {
        int4 c = *(const int4*)&cnt[base + i];
        int4 o;
        o.x = run; run += c.x;
        o.y = run; run += c.y;
        o.z = run; run += c.z;
        o.w = run; run += c.w;
        *(int4*)&start[base + i] = o;
        *(int4*)&cur[base + i]   = o;
    }
}

__global__ void scatter_kernel(const float* __restrict__ unknown,
                               const float* __restrict__ known) {
    int j = blockIdx.x * 256 + threadIdx.x;
    if (j < B_ * M_) {
        int b = j / M_;
        float x = known[3 * j], y = known[3 * j + 1], z = known[3 * j + 2];
        float k2 = __fadd_rn(__fadd_rn(__fmul_rn(x, x), __fmul_rn(y, y)),
                             __fmul_rn(z, z));
        int pos = atomicAdd(&g_kcur[b * CELLS + g_kcell[j]], 1);
        g_ksort[b * M_ + pos] = make_float4(x, y, z, k2);
        g_korig[b * M_ + pos] = j - b * M_;
    } else {
        int q = j - B_ * M_;
        if (q < B_ * N_) {
            int b = q / N_;
            float x = unknown[3 * q], y = unknown[3 * q + 1], z = unknown[3 * q + 2];
            float u2 = __fadd_rn(__fadd_rn(__fmul_rn(x, x), __fmul_rn(y, y)),
                                 __fmul_rn(z, z));
            int pos = atomicAdd(&g_qcur[b * CELLS + g_qcell[q]], 1);
            g_qsort[(size_t)b * N_ + pos] = make_float4(x, y, z, u2);
            g_qorig[(size_t)b * N_ + pos] = q - b * N_;
        }
    }
}

// ---------------------------------------------------------------------------
// Grid-pruned exact 1-NN, thread-per-query (round-10 structure, 64^3 grid).
// d per candidate uses the EXACT reference chain:
//   dot = fmaf(uz,kz, fmaf(uy,ky, ux*kx));  d = fadd(fmaf(-2,dot,u2), k2)
// Selection: (min d, then min ORIGINAL index among bitwise-equal d) ==
// reference's sequential first strict-< min (order-independent).
// Ring stop: unexamined points (Chebyshev >= r) have true dist^2 >=
// ((r-1)*0.125)^2; 4e-3 margin covers fp32 error of the d chain.
// ---------------------------------------------------------------------------
__device__ __forceinline__ void nn_search_body(int gq) {
    const int b = gq / N_;
    const float4 q = g_qsort[gq];
    const int oq = g_qorig[gq];
    const int qx = cellof(q.x), qy = cellof(q.y), qz = cellof(q.z);
    float bd = 3.4e38f; int bi = 0;
    const float4* kp = g_ksort + (size_t)b * M_;
    const int*    ko = g_korig + (size_t)b * M_;
    const int*    st = g_kstart + b * CELLS;
    const int*    ct = g_kcnt + b * CELLS;

    for (int r = 0; r <= GDIM - 1; r++) {
        if (r > 0) {
            float rr = (float)(r - 1) * 0.125f;
            if (bd + 4e-3f <= rr * rr) break;
        }
        int zlo = max(qz - r, 0), zhi = min(qz + r, GDIM - 1);
        for (int cz = zlo; cz <= zhi; cz++) {
            int adz = (cz > qz) ? (cz - qz) : (qz - cz);
            int ylo = max(qy - r, 0), yhi = min(qy + r, GDIM - 1);
            for (int cy = ylo; cy <= yhi; cy++) {
                int ady = (cy > qy) ? (cy - qy) : (qy - cy);
                int xlo, xhi, xstep;
                if (adz == r || ady == r) {
                    xlo = max(qx - r, 0); xhi = min(qx + r, GDIM - 1); xstep = 1;
                } else {
                    xlo = qx - r; xhi = qx + r; xstep = 2 * r;   // r >= 1 here
                }
                for (int cx = xlo; cx <= xhi; cx += xstep) {
                    if ((unsigned)cx > (unsigned)(GDIM - 1)) continue;
                    int cell = (cz * GDIM + cy) * GDIM + cx;
                    int s = st[cell], e = s + ct[cell];
                    for (int jj = s; jj < e; jj++) {
                        float4 k4 = kp[jj];
                        float dot = __fmul_rn(q.x, k4.x);
                        dot = fmaf(q.y, k4.y, dot);
                        dot = fmaf(q.z, k4.z, dot);
                        float d = __fadd_rn(fmaf(-2.0f, dot, q.w), k4.w);
                        int o = ko[jj];
                        if (d < bd) { bd = d; bi = o; }
                        else if (d == bd && o < bi) { bi = o; }
                    }
                }
            }
        }
    }
    g_idx[(size_t)b * N_ + oq] = bi;
}

// ---------------------------------------------------------------------------
// Tensor-core (tf32 mma.sync) fused GEMM body (unchanged).
// ---------------------------------------------------------------------------
template <int KDIM, bool GATHER, bool BN, bool STATS, bool TRANSOUT, int MTOT>
__device__ __forceinline__ void gemm_body(
    uint32_t* SH, int* idbuf,
    int b, int ob0, int ib0, int nbx, int bx,
    const float* __restrict__ W, int ldw, int woff,
    const float* __restrict__ X, int N,
    const float* __restrict__ P,
    const int*   __restrict__ idx,
    const float* __restrict__ bsc,
    const float* __restrict__ bbi,
    float* __restrict__ Y,
    float* __restrict__ part)
{
    const int t   = threadIdx.x;
    const int lane = t & 31, wid = t >> 5;
    const int wo = wid >> 1, wn = wid & 1;
    const int gid = lane >> 2, tig = lane & 3;

    const float* Wp = W + woff;
    const float* Xb = X + (size_t)b * KDIM * N;

    float acc[2][8][4];
#pragma unroll
    for (int m = 0; m < 2; m++)
#pragma unroll
        for (int n = 0; n < 8; n++)
#pragma unroll
            for (int e = 0; e < 4; e++) acc[m][n][e] = 0.f;

    const int w_o   = t >> 1;
    const int w_kq0 = (t & 1) * 16;
    const int w_mt  = w_o >> 4, w_gid = w_o & 7, w_hi = (w_o >> 3) & 1;

    const int x_k   = t >> 3;
    const int x_i0  = (t & 7) * 16;
    const int x_s   = x_k >> 3;
    const int x_tig = x_k & 3, x_hi = (x_k >> 2) & 1;

    constexpr int NKT = KDIM / 32;
    int buf = 0;
    for (int kt = 0; kt < NKT; ++kt) {
        const int k0 = kt * 32;
        uint32_t* Ab = SH + buf * 4096;
        uint32_t* Bb = SH + 8192 + buf * 4096;

        {
            const float* wr = Wp + (size_t)(ob0 + w_o) * ldw + k0 + w_kq0;
#pragma unroll
            for (int j = 0; j < 4; j++) {
                float4 v = *(const float4*)(wr + j * 4);
                uint32_t q[4] = {cvt_tf32(v.x), cvt_tf32(v.y), cvt_tf32(v.z), cvt_tf32(v.w)};
#pragma unroll
                for (int e = 0; e < 4; e++) {
                    int kk = w_kq0 + j * 4 + e;
                    int s = kk >> 3, c = kk & 7;
                    Ab[(((s * 8 + w_mt) * 32 + w_gid * 4 + (c & 3)) << 2)
                       + w_hi + ((c >> 2) << 1)] = q[e];
                }
            }
        }
        {
            const float* xr = Xb + (size_t)(k0 + x_k) * N + ib0 + x_i0;
            float bs = 0.f, bb = 0.f;
            if (BN) { bs = bsc[k0 + x_k]; bb = bbi[k0 + x_k]; }
#pragma unroll
            for (int j = 0; j < 4; j++) {
                float4 v = *(const float4*)(xr + j * 4);
                if (BN) {
                    v.x = fmaxf(fmaf(v.x, bs, bb), 0.f);
                    v.y = fmaxf(fmaf(v.y, bs, bb), 0.f);
                    v.z = fmaxf(fmaf(v.z, bs, bb), 0.f);
                    v.w = fmaxf(fmaf(v.w, bs, bb), 0.f);
                }
                uint32_t q[4] = {cvt_tf32(v.x), cvt_tf32(v.y), cvt_tf32(v.z), cvt_tf32(v.w)};
#pragma unroll
                for (int e = 0; e < 4; e++) {
                    int i = x_i0 + j * 4 + e;
                    int nt = i >> 3, gg = i & 7;
                    Bb[(((x_s * 8 + (nt >> 1)) * 32 + gg * 4 + x_tig) << 2)
                       + (nt & 1) * 2 + x_hi] = q[e];
                }
            }
        }
        __syncthreads();
#pragma unroll
        for (int s = 0; s < 4; s++) {
            uint4 af[2];
            af[0] = *(const uint4*)&Ab[((s * 8 + wo * 2 + 0) * 32 + lane) << 2];
            af[1] = *(const uint4*)&Ab[((s * 8 + wo * 2 + 1) * 32 + lane) << 2];
            uint4 bf[4];
#pragma unroll
            for (int p = 0; p < 4; p++)
                bf[p] = *(const uint4*)&Bb[((s * 8 + wn * 4 + p) * 32 + lane) << 2];
#pragma unroll
            for (int m = 0; m < 2; m++)
#pragma unroll
                for (int p = 0; p < 4; p++) {
                    mma_tf32(acc[m][2 * p],     (const uint32_t*)&af[m], bf[p].x, bf[p].y);
                    mma_tf32(acc[m][2 * p + 1], (const uint32_t*)&af[m], bf[p].z, bf[p].w);
                }
        }
        buf ^= 1;
    }

    const int o_base = ob0 + wo * 32;
    const int i_base = ib0 + wn * 64;

    if (GATHER) {
        __syncthreads();
        if (t < 128) idbuf[t] = idx[(size_t)b * N + ib0 + t];
        __syncthreads();
        float* G = (float*)SH;
#pragma unroll
        for (int j = 0; j < 16; j++) {
            int lin = t + j * 256;
            int r = lin >> 5, c4 = (lin & 31) << 2;
            const float* src = P + ((size_t)b * M_ + idbuf[r]) * MTOT + ob0 + c4;
            *(float4*)&G[r * 128 + c4] = *(const float4*)src;
        }
        __syncthreads();
        const int i0l = wn * 64 + tig * 2;
        const int o0l = wo * 32 + gid;
#pragma unroll
        for (int m = 0; m < 2; m++) {
            int oo = o0l + m * 16;
#pragma unroll
            for (int n = 0; n < 8; n++) {
                int ii = i0l + n * 8;
                acc[m][n][0] += G[ii * 128 + oo];
                acc[m][n][1] += G[(ii + 1) * 128 + oo];
                acc[m][n][2] += G[ii * 128 + oo + 8];
                acc[m][n][3] += G[(ii + 1) * 128 + oo + 8];
            }
        }
    }

    if (TRANSOUT) {
#pragma unroll
        for (int m = 0; m < 2; m++)
#pragma unroll
            for (int n = 0; n < 8; n++) {
                int i_ = i_base + n * 8 + tig * 2;
                int o_ = o_base + m * 16 + gid;
                float* Yr = Y + ((size_t)b * N + i_) * MTOT;
                Yr[o_]            = acc[m][n][0];
                Yr[MTOT + o_]     = acc[m][n][1];
                Yr[o_ + 8]        = acc[m][n][2];
                Yr[MTOT + o_ + 8] = acc[m][n][3];
            }
    } else {
#pragma unroll
        for (int m = 0; m < 2; m++) {
            float* Y0 = Y + ((size_t)b * MTOT + o_base + m * 16 + gid) * N + i_base + tig * 2;
            float* Y8 = Y0 + (size_t)8 * N;
#pragma unroll
            for (int n = 0; n < 8; n++) {
                *(float2*)(Y0 + n * 8) = make_float2(acc[m][n][0], acc[m][n][1]);
                *(float2*)(Y8 + n * 8) = make_float2(acc[m][n][2], acc[m][n][3]);
            }
        }
    }

    if (STATS) {
        float s1[2][2], s2[2][2];
#pragma unroll
        for (int m = 0; m < 2; m++) {
            float a0 = 0.f, q0 = 0.f, a1 = 0.f, q1 = 0.f;
#pragma unroll
            for (int n = 0; n < 8; n++) {
                a0 += acc[m][n][0]; q0 = fmaf(acc[m][n][0], acc[m][n][0], q0);
                a0 += acc[m][n][1]; q0 = fmaf(acc[m][n][1], acc[m][n][1], q0);
                a1 += acc[m][n][2]; q1 = fmaf(acc[m][n][2], acc[m][n][2], q1);
                a1 += acc[m][n][3]; q1 = fmaf(acc[m][n][3], acc[m][n][3], q1);
            }
            s1[m][0] = a0; s2[m][0] = q0; s1[m][1] = a1; s2[m][1] = q1;
        }
#pragma unroll
        for (int m = 0; m < 2; m++)
#pragma unroll
            for (int h = 0; h < 2; h++) {
#pragma unroll
                for (int off = 1; off <= 2; off <<= 1) {
                    s1[m][h] += __shfl_xor_sync(0xffffffffu, s1[m][h], off);
                    s2[m][h] += __shfl_xor_sync(0xffffffffu, s2[m][h], off);
                }
            }
        float* sb1 = (float*)SH;
        float* sb2 = sb1 + 256;
        __syncthreads();
        if (tig == 0) {
#pragma unroll
            for (int m = 0; m < 2; m++)
#pragma unroll
                for (int h = 0; h < 2; h++) {
                    int ol = wo * 32 + m * 16 + h * 8 + gid;
                    sb1[wn * 128 + ol] = s1[m][h];
                    sb2[wn * 128 + ol] = s2[m][h];
                }
        }
        __syncthreads();
        if (t < 128) {
            float tot = sb1[t] + sb1[128 + t];
            part[(((size_t)b * MTOT + ob0 + t) * nbx + bx) * 2 + 0] = tot;
        } else {
            int o = t - 128;
            float tot = sb2[o] + sb2[128 + o];
            part[(((size_t)b * MTOT + ob0 + o) * nbx + bx) * 2 + 1] = tot;
        }
    }
}

// ---------------------------------------------------------------------------
// Standalone GEMM kernel (K3, K5)
// ---------------------------------------------------------------------------
template <int KDIM, bool GATHER, bool BN, bool STATS, bool TRANSOUT, int MTOT>
__global__ void __launch_bounds__(256, 2) gemm_kernel(
    const float* __restrict__ W, int ldw, int woff,
    const float* __restrict__ X, int N,
    const float* __restrict__ P,
    const int*   __restrict__ idx,
    const float* __restrict__ bsc,
    const float* __restrict__ bbi,
    float* __restrict__ Y,
    float* __restrict__ part)
{
    __shared__ __align__(16) uint32_t SH[16384];
    __shared__ int idbuf[128];
    gemm_body<KDIM, GATHER, BN, STATS, TRANSOUT, MTOT>(
        SH, idbuf, blockIdx.z, blockIdx.y * 128, blockIdx.x * 128,
        gridDim.x, blockIdx.x,
        W, ldw, woff, X, N, P, idx, bsc, bbi, Y, part);
}

// ---------------------------------------------------------------------------
// FUSED kernel: bids [0,512) = grid-pruned 1-NN (256 queries/CTA, thread-per-
// query); bids [512,1024) = K2 (P_t = (w1a @ kf)^T).
// ---------------------------------------------------------------------------
__global__ void __launch_bounds__(256, 2) fused_nn_k2_kernel(
    const float* __restrict__ w1,
    const float* __restrict__ kf,
    float* __restrict__ P)
{
    __shared__ __align__(16) uint32_t SH[16384];
    __shared__ int idbuf[128];
    const int bid = blockIdx.x;
    if (bid < 512) {
        nn_search_body(bid * 256 + threadIdx.x);
    } else {
        const int g  = bid - 512;
        const int bx = g & 127;
        const int oy = (g >> 7) & 1;
        const int b  = g >> 8;
        gemm_body<C2_, false, false, false, true, H1_>(
            SH, idbuf, b, oy * 128, bx * 128, 128, bx,
            w1, 384, 0, kf, M_, nullptr, nullptr, nullptr, nullptr,
            P, nullptr);
    }
}

// ---------------------------------------------------------------------------
// Finalize BN stats: one block per channel
// ---------------------------------------------------------------------------
template <int MTOT>
__global__ void __launch_bounds__(128) fin_kernel(
    const float* __restrict__ part,
    const float* __restrict__ gamma, const float* __restrict__ beta,
    float* __restrict__ sc, float* __restrict__ bi, float invN)
{
    const int o = blockIdx.x;
    const int t = threadIdx.x;
    float s1 = 0.f, s2 = 0.f;
    for (int b = 0; b < B_; b++) {
        const float* p = part + ((size_t)b * MTOT + o) * NT_ * 2;
        for (int q = t; q < NT_; q += 128) {
            s1 += p[q * 2 + 0];
            s2 += p[q * 2 + 1];
        }
    }
#pragma unroll
    for (int off = 16; off; off >>= 1) {
        s1 += __shfl_down_sync(0xffffffffu, s1, off);
        s2 += __shfl_down_sync(0xffffffffu, s2, off);
    }
    __shared__ float r1[4], r2[4];
    if ((t & 31) == 0) { r1[t >> 5] = s1; r2[t >> 5] = s2; }
    __syncthreads();
    if (t == 0) {
        s1 = r1[0] + r1[1] + r1[2] + r1[3];
        s2 = r2[0] + r2[1] + r2[2] + r2[3];
        float mean = s1 * invN;
        float var  = s2 * invN - mean * mean;
        float rstd = rsqrtf(var + EPS_);
        float s    = gamma[o] * rstd;
        sc[o] = s;
        bi[o] = beta[o] - mean * s;
    }
}

// ---------------------------------------------------------------------------
// Final elementwise BN+ReLU in-place on d_out
// ---------------------------------------------------------------------------
__global__ void __launch_bounds__(256) bnfin_kernel(
    float* __restrict__ Y, const float* __restrict__ sc, const float* __restrict__ bi)
{
    int row = blockIdx.y;
    int ch  = row & (H2_ - 1);
    size_t base = (size_t)row * N_;
    int i = (blockIdx.x * 256 + threadIdx.x) * 4;
    float4 v = *(float4*)(Y + base + i);
    float s = sc[ch], b = bi[ch];
    v.x = fmaxf(fmaf(v.x, s, b), 0.f);
    v.y = fmaxf(fmaf(v.y, s, b), 0.f);
    v.z = fmaxf(fmaf(v.z, s, b), 0.f);
    v.w = fmaxf(fmaf(v.w, s, b), 0.f);
    *(float4*)(Y + base + i) = v;
}

// ---------------------------------------------------------------------------
// Launch
// ---------------------------------------------------------------------------
extern "C" void kernel_launch(void* const* d_in, const int* in_sizes, int n_in,
                              void* d_out, int out_size)
{
    const float* unknown = (const float*)d_in[0];
    const float* known   = (const float*)d_in[1];
    const float* uf      = (const float*)d_in[2];
    const float* kf      = (const float*)d_in[3];
    const float* w1      = (const float*)d_in[4];
    const float* gamma1  = (const float*)d_in[5];
    const float* beta1   = (const float*)d_in[6];
    const float* w2      = (const float*)d_in[7];
    const float* gamma2  = (const float*)d_in[8];
    const float* beta2   = (const float*)d_in[9];
    float* out = (float*)d_out;

    float *pP, *ph, *pp1, *pp2, *ps1, *pb1, *ps2, *pb2;
    int* pidx;
    cudaGetSymbolAddress((void**)&pP,   g_P);
    cudaGetSymbolAddress((void**)&ph,   g_h);
    cudaGetSymbolAddress((void**)&pp1,  g_part1);
    cudaGetSymbolAddress((void**)&pp2,  g_part2);
    cudaGetSymbolAddress((void**)&ps1,  g_scale1);
    cudaGetSymbolAddress((void**)&pb1,  g_bias1);
    cudaGetSymbolAddress((void**)&ps2,  g_scale2);
    cudaGetSymbolAddress((void**)&pb2,  g_bias2);
    cudaGetSymbolAddress((void**)&pidx, g_idx);

    const float invN = 1.0f / (float)(B_ * N_);

    // grid binning for pruned 1-NN (64^3)
    zero_kernel<<<(B_ * CELLS) / 256, 256>>>();
    hist_kernel<<<(B_ * (M_ + N_)) / 256, 256>>>(unknown, known);
    scan_kernel<<<4, 1024>>>();
    scatter_kernel<<<(B_ * (M_ + N_)) / 256, 256>>>(unknown, known);

    // 1-NN (bids 0..511) + K2 P_t-GEMM (bids 512..1023) in one launch
    fused_nn_k2_kernel<<<1024, 256>>>(w1, kf, pP);

    // h = w1[:, 256:] @ unknow_feats + gather(P_t, idx); stats1
    gemm_kernel<C1_, true, false, true, false, H1_>
        <<<dim3(N_ / 128, H1_ / 128, B_), 256>>>(
            w1, 384, C2_, uf, N_, pP, pidx, nullptr, nullptr, ph, pp1);

    fin_kernel<H1_><<<H1_, 128>>>(pp1, gamma1, beta1, ps1, pb1, invN);

    // out_pre = w2 @ relu(bn1(h)); stats2
    gemm_kernel<H1_, false, true, true, false, H2_>
        <<<dim3(N_ / 128, H2_ / 128, B_), 256>>>(
            w2, 256, 0, ph, N_, nullptr, nullptr, ps1, pb1, out, pp2);

    fin_kernel<H2_><<<H2_, 128>>>(pp2, gamma2, beta2, ps2, pb2, invN);

    bnfin_kernel<<<dim3(N_ / 1024, B_ * H2_), 256>>>(out, ps2, pb2);
}

// round 13
// speedup vs baseline: 3.1651x; 3.1651x over previous
#include <cuda_runtime.h>
#include <cstdint>

// ---------------------------------------------------------------------------
// Problem constants
// ---------------------------------------------------------------------------
#define B_   2
#define N_   65536
#define M_   16384
#define C1_  128
#define C2_  256
#define H1_  256
#define H2_  128
#define NT_  512
#define EPS_ 1e-5f
#define CELLS 32768          // 32^3 grid per batch, h = 0.25

// ---------------------------------------------------------------------------
// Scratch (device globals -- no allocation allowed)
// ---------------------------------------------------------------------------
__device__ int    g_idx[B_ * N_];
__device__ float  g_P[(size_t)B_ * M_ * H1_];      // TRANSPOSED: [b][m][o]
__device__ float  g_h[(size_t)B_ * H1_ * N_];
__device__ float  g_part1[(size_t)B_ * H1_ * NT_ * 2];
__device__ float  g_part2[(size_t)B_ * H2_ * NT_ * 2];
__device__ float  g_scale1[H1_], g_bias1[H1_];
__device__ float  g_scale2[H2_], g_bias2[H2_];

// grid-NN scratch
__device__ int    g_kcnt[B_ * CELLS], g_kstart[B_ * CELLS], g_kcur[B_ * CELLS];
__device__ int2   g_ksc[B_ * CELLS];               // merged (start, cnt)
__device__ int    g_qcnt[B_ * CELLS], g_qstart[B_ * CELLS], g_qcur[B_ * CELLS];
__device__ int    g_kcell[B_ * M_],  g_qcell[B_ * N_];
__device__ __align__(16) float4 g_ksort[B_ * M_];
__device__ __align__(16) float4 g_qsort[B_ * N_];
__device__ int    g_korig[B_ * M_], g_qorig[B_ * N_];

// ---------------------------------------------------------------------------
// helpers
// ---------------------------------------------------------------------------
__device__ __forceinline__ uint32_t cvt_tf32(float f) {
    uint32_t u;
    asm("cvt.rna.tf32.f32 %0, %1;" : "=r"(u) : "f"(f));
    return u;
}
__device__ __forceinline__ void mma_tf32(float* c, const uint32_t* a,
                                         uint32_t b0, uint32_t b1) {
    asm volatile(
        "mma.sync.aligned.m16n8k8.row.col.f32.tf32.tf32.f32 "
        "{%0,%1,%2,%3}, {%4,%5,%6,%7}, {%8,%9}, {%0,%1,%2,%3};\n"
        : "+f"(c[0]), "+f"(c[1]), "+f"(c[2]), "+f"(c[3])
        : "r"(a[0]), "r"(a[1]), "r"(a[2]), "r"(a[3]), "r"(b0), "r"(b1));
}
__device__ __forceinline__ int cellof(float v) {
    int c = __float2int_rd((v + 4.0f) * 4.0f);
    return min(31, max(0, c));
}

// ---------------------------------------------------------------------------
// Binning: zero counters -> histogram -> scan -> scatter
// ---------------------------------------------------------------------------
__global__ void zero_kernel() {
    int i = blockIdx.x * 256 + threadIdx.x;
    if (i < B_ * CELLS) { g_kcnt[i] = 0; g_qcnt[i] = 0; }
}

__global__ void hist_kernel(const float* __restrict__ unknown,
                            const float* __restrict__ known) {
    int j = blockIdx.x * 256 + threadIdx.x;
    if (j < B_ * M_) {
        float x = known[3 * j], y = known[3 * j + 1], z = known[3 * j + 2];
        int cell = (cellof(z) * 32 + cellof(y)) * 32 + cellof(x);
        g_kcell[j] = cell;
        atomicAdd(&g_kcnt[(j / M_) * CELLS + cell], 1);
    } else {
        int q = j - B_ * M_;
        if (q < B_ * N_) {
            float x = unknown[3 * q], y = unknown[3 * q + 1], z = unknown[3 * q + 2];
            int cell = (cellof(z) * 32 + cellof(y)) * 32 + cellof(x);
            g_qcell[q] = cell;
            atomicAdd(&g_qcnt[(q / N_) * CELLS + cell], 1);
        }
    }
}

// one block per (array, batch): 0,1 = knowns b0/b1; 2,3 = queries b0/b1
__global__ void __launch_bounds__(1024) scan_kernel() {
    const int w = blockIdx.x;
    int* cnt;  int* start;  int* cur;
    int2* merged = nullptr;
    if (w < 2) {
        cnt = g_kcnt + w * CELLS; start = g_kstart + w * CELLS;
        cur = g_kcur + w * CELLS; merged = g_ksc + w * CELLS;
    } else {
        int b = w - 2;
        cnt = g_qcnt + b * CELLS; start = g_qstart + b * CELLS;
        cur = g_qcur + b * CELLS;
    }
    const int t = threadIdx.x;
    int loc[32]; int s = 0;
#pragma unroll
    for (int i = 0; i < 32; i++) { loc[i] = s; s += cnt[t * 32 + i]; }
    const int lane = t & 31, wid = t >> 5;
    int v = s;
#pragma unroll
    for (int off = 1; off < 32; off <<= 1) {
        int n = __shfl_up_sync(0xffffffffu, v, off);
        if (lane >= off) v += n;
    }
    __shared__ int ws[32];
    if (lane == 31) ws[wid] = v;
    __syncthreads();
    if (wid == 0) {
        int x = ws[lane];
#pragma unroll
        for (int off = 1; off < 32; off <<= 1) {
            int n = __shfl_up_sync(0xffffffffu, x, off);
            if (lane >= off) x += n;
        }
        ws[lane] = x;
    }
    __syncthreads();
    int base = v - s + (wid > 0 ? ws[wid - 1] : 0);
#pragma unroll
    for (int i = 0; i < 32; i++) {
        int val = base + loc[i];
        start[t * 32 + i] = val;
        cur[t * 32 + i] = val;
        if (merged) merged[t * 32 + i] = make_int2(val, cnt[t * 32 + i]);
    }
}

__global__ void scatter_kernel(const float* __restrict__ unknown,
                               const float* __restrict__ known) {
    int j = blockIdx.x * 256 + threadIdx.x;
    if (j < B_ * M_) {
        int b = j / M_;
        float x = known[3 * j], y = known[3 * j + 1], z = known[3 * j + 2];
        float k2 = __fadd_rn(__fadd_rn(__fmul_rn(x, x), __fmul_rn(y, y)),
                             __fmul_rn(z, z));
        int pos = atomicAdd(&g_kcur[b * CELLS + g_kcell[j]], 1);
        g_ksort[b * M_ + pos] = make_float4(x, y, z, k2);
        g_korig[b * M_ + pos] = j - b * M_;
    } else {
        int q = j - B_ * M_;
        if (q < B_ * N_) {
            int b = q / N_;
            float x = unknown[3 * q], y = unknown[3 * q + 1], z = unknown[3 * q + 2];
            float u2 = __fadd_rn(__fadd_rn(__fmul_rn(x, x), __fmul_rn(y, y)),
                                 __fmul_rn(z, z));
            int pos = atomicAdd(&g_qcur[b * CELLS + g_qcell[q]], 1);
            g_qsort[(size_t)b * N_ + pos] = make_float4(x, y, z, u2);
            g_qorig[(size_t)b * N_ + pos] = q - b * N_;
        }
    }
}

// ---------------------------------------------------------------------------
// Grid-pruned exact 1-NN, thread-per-query (proven round-10 structure).
// d per candidate uses the EXACT reference chain:
//   dot = fmaf(uz,kz, fmaf(uy,ky, ux*kx));  d = fadd(fmaf(-2,dot,u2), k2)
// Selection: (min d, then min ORIGINAL index among bitwise-equal d) ==
// reference's sequential first strict-< min (order-independent).
// Ring stop: unexamined points (Chebyshev >= r) have true dist^2 >=
// ((r-1)*0.25)^2; 4e-3 margin covers fp32 error of the d chain.
// Memory-op reductions vs round 10: merged int2 (start,cnt) descriptor
// (one LDG.64 per cell), and ko[] loaded ONLY on the rare d<=bd paths.
// ---------------------------------------------------------------------------
__device__ __forceinline__ void nn_search_body(int gq) {
    const int b = gq / N_;
    const float4 q = g_qsort[gq];
    const int oq = g_qorig[gq];
    const int qx = cellof(q.x), qy = cellof(q.y), qz = cellof(q.z);
    float bd = 3.4e38f; int bi = 0;
    const float4* kp = g_ksort + (size_t)b * M_;
    const int*    ko = g_korig + (size_t)b * M_;
    const int2*   sc = g_ksc + b * CELLS;

    for (int r = 0; r <= 31; r++) {
        if (r > 0) {
            float rr = (float)(r - 1) * 0.25f;
            if (bd + 4e-3f <= rr * rr) break;
        }
        int zlo = max(qz - r, 0), zhi = min(qz + r, 31);
        for (int cz = zlo; cz <= zhi; cz++) {
            int adz = (cz > qz) ? (cz - qz) : (qz - cz);
            int ylo = max(qy - r, 0), yhi = min(qy + r, 31);
            for (int cy = ylo; cy <= yhi; cy++) {
                int ady = (cy > qy) ? (cy - qy) : (qy - cy);
                int xlo, xhi, xstep;
                if (adz == r || ady == r) {
                    xlo = max(qx - r, 0); xhi = min(qx + r, 31); xstep = 1;
                } else {
                    xlo = qx - r; xhi = qx + r; xstep = 2 * r;   // r >= 1 here
                }
                for (int cx = xlo; cx <= xhi; cx += xstep) {
                    if ((unsigned)cx > 31u) continue;
                    int cell = (cz * 32 + cy) * 32 + cx;
                    int2 se = sc[cell];                   // one LDG.64
                    int s = se.x, e = se.x + se.y;
                    for (int jj = s; jj < e; jj++) {
                        float4 k4 = kp[jj];
                        float dot = __fmul_rn(q.x, k4.x);
                        dot = fmaf(q.y, k4.y, dot);
                        dot = fmaf(q.z, k4.z, dot);
                        float d = __fadd_rn(fmaf(-2.0f, dot, q.w), k4.w);
                        if (d < bd) { bd = d; bi = ko[jj]; }
                        else if (d == bd) {
                            int o = ko[jj];
                            if (o < bi) bi = o;
                        }
                    }
                }
            }
        }
    }
    g_idx[(size_t)b * N_ + oq] = bi;
}

// ---------------------------------------------------------------------------
// Tensor-core (tf32 mma.sync) fused GEMM body (unchanged, proven).
// ---------------------------------------------------------------------------
template <int KDIM, bool GATHER, bool BN, bool STATS, bool TRANSOUT, int MTOT>
__device__ __forceinline__ void gemm_body(
    uint32_t* SH, int* idbuf,
    int b, int ob0, int ib0, int nbx, int bx,
    const float* __restrict__ W, int ldw, int woff,
    const float* __restrict__ X, int N,
    const float* __restrict__ P,
    const int*   __restrict__ idx,
    const float* __restrict__ bsc,
    const float* __restrict__ bbi,
    float* __restrict__ Y,
    float* __restrict__ part)
{
    const int t   = threadIdx.x;
    const int lane = t & 31, wid = t >> 5;
    const int wo = wid >> 1, wn = wid & 1;
    const int gid = lane >> 2, tig = lane & 3;

    const float* Wp = W + woff;
    const float* Xb = X + (size_t)b * KDIM * N;

    float acc[2][8][4];
#pragma unroll
    for (int m = 0; m < 2; m++)
#pragma unroll
        for (int n = 0; n < 8; n++)
#pragma unroll
            for (int e = 0; e < 4; e++) acc[m][n][e] = 0.f;

    const int w_o   = t >> 1;
    const int w_kq0 = (t & 1) * 16;
    const int w_mt  = w_o >> 4, w_gid = w_o & 7, w_hi = (w_o >> 3) & 1;

    const int x_k   = t >> 3;
    const int x_i0  = (t & 7) * 16;
    const int x_s   = x_k >> 3;
    const int x_tig = x_k & 3, x_hi = (x_k >> 2) & 1;

    constexpr int NKT = KDIM / 32;
    int buf = 0;
    for (int kt = 0; kt < NKT; ++kt) {
        const int k0 = kt * 32;
        uint32_t* Ab = SH + buf * 4096;
        uint32_t* Bb = SH + 8192 + buf * 4096;

        {
            const float* wr = Wp + (size_t)(ob0 + w_o) * ldw + k0 + w_kq0;
#pragma unroll
            for (int j = 0; j < 4; j++) {
                float4 v = *(const float4*)(wr + j * 4);
                uint32_t q[4] = {cvt_tf32(v.x), cvt_tf32(v.y), cvt_tf32(v.z), cvt_tf32(v.w)};
#pragma unroll
                for (int e = 0; e < 4; e++) {
                    int kk = w_kq0 + j * 4 + e;
                    int s = kk >> 3, c = kk & 7;
                    Ab[(((s * 8 + w_mt) * 32 + w_gid * 4 + (c & 3)) << 2)
                       + w_hi + ((c >> 2) << 1)] = q[e];
                }
            }
        }
        {
            const float* xr = Xb + (size_t)(k0 + x_k) * N + ib0 + x_i0;
            float bs = 0.f, bb = 0.f;
            if (BN) { bs = bsc[k0 + x_k]; bb = bbi[k0 + x_k]; }
#pragma unroll
            for (int j = 0; j < 4; j++) {
                float4 v = *(const float4*)(xr + j * 4);
                if (BN) {
                    v.x = fmaxf(fmaf(v.x, bs, bb), 0.f);
                    v.y = fmaxf(fmaf(v.y, bs, bb), 0.f);
                    v.z = fmaxf(fmaf(v.z, bs, bb), 0.f);
                    v.w = fmaxf(fmaf(v.w, bs, bb), 0.f);
                }
                uint32_t q[4] = {cvt_tf32(v.x), cvt_tf32(v.y), cvt_tf32(v.z), cvt_tf32(v.w)};
#pragma unroll
                for (int e = 0; e < 4; e++) {
                    int i = x_i0 + j * 4 + e;
                    int nt = i >> 3, gg = i & 7;
                    Bb[(((x_s * 8 + (nt >> 1)) * 32 + gg * 4 + x_tig) << 2)
                       + (nt & 1) * 2 + x_hi] = q[e];
                }
            }
        }
        __syncthreads();
#pragma unroll
        for (int s = 0; s < 4; s++) {
            uint4 af[2];
            af[0] = *(const uint4*)&Ab[((s * 8 + wo * 2 + 0) * 32 + lane) << 2];
            af[1] = *(const uint4*)&Ab[((s * 8 + wo * 2 + 1) * 32 + lane) << 2];
            uint4 bf[4];
#pragma unroll
            for (int p = 0; p < 4; p++)
                bf[p] = *(const uint4*)&Bb[((s * 8 + wn * 4 + p) * 32 + lane) << 2];
#pragma unroll
            for (int m = 0; m < 2; m++)
#pragma unroll
                for (int p = 0; p < 4; p++) {
                    mma_tf32(acc[m][2 * p],     (const uint32_t*)&af[m], bf[p].x, bf[p].y);
                    mma_tf32(acc[m][2 * p + 1], (const uint32_t*)&af[m], bf[p].z, bf[p].w);
                }
        }
        buf ^= 1;
    }

    const int o_base = ob0 + wo * 32;
    const int i_base = ib0 + wn * 64;

    if (GATHER) {
        __syncthreads();
        if (t < 128) idbuf[t] = idx[(size_t)b * N + ib0 + t];
        __syncthreads();
        float* G = (float*)SH;
#pragma unroll
        for (int j = 0; j < 16; j++) {
            int lin = t + j * 256;
            int r = lin >> 5, c4 = (lin & 31) << 2;
            const float* src = P + ((size_t)b * M_ + idbuf[r]) * MTOT + ob0 + c4;
            *(float4*)&G[r * 128 + c4] = *(const float4*)src;
        }
        __syncthreads();
        const int i0l = wn * 64 + tig * 2;
        const int o0l = wo * 32 + gid;
#pragma unroll
        for (int m = 0; m < 2; m++) {
            int oo = o0l + m * 16;
#pragma unroll
            for (int n = 0; n < 8; n++) {
                int ii = i0l + n * 8;
                acc[m][n][0] += G[ii * 128 + oo];
                acc[m][n][1] += G[(ii + 1) * 128 + oo];
                acc[m][n][2] += G[ii * 128 + oo + 8];
                acc[m][n][3] += G[(ii + 1) * 128 + oo + 8];
            }
        }
    }

    if (TRANSOUT) {
#pragma unroll
        for (int m = 0; m < 2; m++)
#pragma unroll
            for (int n = 0; n < 8; n++) {
                int i_ = i_base + n * 8 + tig * 2;
                int o_ = o_base + m * 16 + gid;
                float* Yr = Y + ((size_t)b * N + i_) * MTOT;
                Yr[o_]            = acc[m][n][0];
                Yr[MTOT + o_]     = acc[m][n][1];
                Yr[o_ + 8]        = acc[m][n][2];
                Yr[MTOT + o_ + 8] = acc[m][n][3];
            }
    } else {
#pragma unroll
        for (int m = 0; m < 2; m++) {
            float* Y0 = Y + ((size_t)b * MTOT + o_base + m * 16 + gid) * N + i_base + tig * 2;
            float* Y8 = Y0 + (size_t)8 * N;
#pragma unroll
            for (int n = 0; n < 8; n++) {
                *(float2*)(Y0 + n * 8) = make_float2(acc[m][n][0], acc[m][n][1]);
                *(float2*)(Y8 + n * 8) = make_float2(acc[m][n][2], acc[m][n][3]);
            }
        }
    }

    if (STATS) {
        float s1[2][2], s2[2][2];
#pragma unroll
        for (int m = 0; m < 2; m++) {
            float a0 = 0.f, q0 = 0.f, a1 = 0.f, q1 = 0.f;
#pragma unroll
            for (int n = 0; n < 8; n++) {
                a0 += acc[m][n][0]; q0 = fmaf(acc[m][n][0], acc[m][n][0], q0);
                a0 += acc[m][n][1]; q0 = fmaf(acc[m][n][1], acc[m][n][1], q0);
                a1 += acc[m][n][2]; q1 = fmaf(acc[m][n][2], acc[m][n][2], q1);
                a1 += acc[m][n][3]; q1 = fmaf(acc[m][n][3], acc[m][n][3], q1);
            }
            s1[m][0] = a0; s2[m][0] = q0; s1[m][1] = a1; s2[m][1] = q1;
        }
#pragma unroll
        for (int m = 0; m < 2; m++)
#pragma unroll
            for (int h = 0; h < 2; h++) {
#pragma unroll
                for (int off = 1; off <= 2; off <<= 1) {
                    s1[m][h] += __shfl_xor_sync(0xffffffffu, s1[m][h], off);
                    s2[m][h] += __shfl_xor_sync(0xffffffffu, s2[m][h], off);
                }
            }
        float* sb1 = (float*)SH;
        float* sb2 = sb1 + 256;
        __syncthreads();
        if (tig == 0) {
#pragma unroll
            for (int m = 0; m < 2; m++)
#pragma unroll
                for (int h = 0; h < 2; h++) {
                    int ol = wo * 32 + m * 16 + h * 8 + gid;
                    sb1[wn * 128 + ol] = s1[m][h];
                    sb2[wn * 128 + ol] = s2[m][h];
                }
        }
        __syncthreads();
        if (t < 128) {
            float tot = sb1[t] + sb1[128 + t];
            part[(((size_t)b * MTOT + ob0 + t) * nbx + bx) * 2 + 0] = tot;
        } else {
            int o = t - 128;
            float tot = sb2[o] + sb2[128 + o];
            part[(((size_t)b * MTOT + ob0 + o) * nbx + bx) * 2 + 1] = tot;
        }
    }
}

// ---------------------------------------------------------------------------
// Standalone GEMM kernel (K3, K5)
// ---------------------------------------------------------------------------
template <int KDIM, bool GATHER, bool BN, bool STATS, bool TRANSOUT, int MTOT>
__global__ void __launch_bounds__(256, 2) gemm_kernel(
    const float* __restrict__ W, int ldw, int woff,
    const float* __restrict__ X, int N,
    const float* __restrict__ P,
    const int*   __restrict__ idx,
    const float* __restrict__ bsc,
    const float* __restrict__ bbi,
    float* __restrict__ Y,
    float* __restrict__ part)
{
    __shared__ __align__(16) uint32_t SH[16384];
    __shared__ int idbuf[128];
    gemm_body<KDIM, GATHER, BN, STATS, TRANSOUT, MTOT>(
        SH, idbuf, blockIdx.z, blockIdx.y * 128, blockIdx.x * 128,
        gridDim.x, blockIdx.x,
        W, ldw, woff, X, N, P, idx, bsc, bbi, Y, part);
}

// ---------------------------------------------------------------------------
// FUSED kernel: bids [0,512) = grid-pruned 1-NN (256 queries/CTA, thread-per-
// query); bids [512,1024) = K2 (P_t = (w1a @ kf)^T).
// ---------------------------------------------------------------------------
__global__ void __launch_bounds__(256, 2) fused_nn_k2_kernel(
    const float* __restrict__ w1,
    const float* __restrict__ kf,
    float* __restrict__ P)
{
    __shared__ __align__(16) uint32_t SH[16384];
    __shared__ int idbuf[128];
    const int bid = blockIdx.x;
    if (bid < 512) {
        nn_search_body(bid * 256 + threadIdx.x);
    } else {
        const int g  = bid - 512;
        const int bx = g & 127;
        const int oy = (g >> 7) & 1;
        const int b  = g >> 8;
        gemm_body<C2_, false, false, false, true, H1_>(
            SH, idbuf, b, oy * 128, bx * 128, 128, bx,
            w1, 384, 0, kf, M_, nullptr, nullptr, nullptr, nullptr,
            P, nullptr);
    }
}

// ---------------------------------------------------------------------------
// Finalize BN stats: one block per channel
// ---------------------------------------------------------------------------
template <int MTOT>
__global__ void __launch_bounds__(128) fin_kernel(
    const float* __restrict__ part,
    const float* __restrict__ gamma, const float* __restrict__ beta,
    float* __restrict__ sc, float* __restrict__ bi, float invN)
{
    const int o = blockIdx.x;
    const int t = threadIdx.x;
    float s1 = 0.f, s2 = 0.f;
    for (int b = 0; b < B_; b++) {
        const float* p = part + ((size_t)b * MTOT + o) * NT_ * 2;
        for (int q = t; q < NT_; q += 128) {
            s1 += p[q * 2 + 0];
            s2 += p[q * 2 + 1];
        }
    }
#pragma unroll
    for (int off = 16; off; off >>= 1) {
        s1 += __shfl_down_sync(0xffffffffu, s1, off);
        s2 += __shfl_down_sync(0xffffffffu, s2, off);
    }
    __shared__ float r1[4], r2[4];
    if ((t & 31) == 0) { r1[t >> 5] = s1; r2[t >> 5] = s2; }
    __syncthreads();
    if (t == 0) {
        s1 = r1[0] + r1[1] + r1[2] + r1[3];
        s2 = r2[0] + r2[1] + r2[2] + r2[3];
        float mean = s1 * invN;
        float var  = s2 * invN - mean * mean;
        float rstd = rsqrtf(var + EPS_);
        float s    = gamma[o] * rstd;
        sc[o] = s;
        bi[o] = beta[o] - mean * s;
    }
}

// ---------------------------------------------------------------------------
// Final elementwise BN+ReLU in-place on d_out
// ---------------------------------------------------------------------------
__global__ void __launch_bounds__(256) bnfin_kernel(
    float* __restrict__ Y, const float* __restrict__ sc, const float* __restrict__ bi)
{
    int row = blockIdx.y;
    int ch  = row & (H2_ - 1);
    size_t base = (size_t)row * N_;
    int i = (blockIdx.x * 256 + threadIdx.x) * 4;
    float4 v = *(float4*)(Y + base + i);
    float s = sc[ch], b = bi[ch];
    v.x = fmaxf(fmaf(v.x, s, b), 0.f);
    v.y = fmaxf(fmaf(v.y, s, b), 0.f);
    v.z = fmaxf(fmaf(v.z, s, b), 0.f);
    v.w = fmaxf(fmaf(v.w, s, b), 0.f);
    *(float4*)(Y + base + i) = v;
}

// ---------------------------------------------------------------------------
// Launch
// ---------------------------------------------------------------------------
extern "C" void kernel_launch(void* const* d_in, const int* in_sizes, int n_in,
                              void* d_out, int out_size)
{
    const float* unknown = (const float*)d_in[0];
    const float* known   = (const float*)d_in[1];
    const float* uf      = (const float*)d_in[2];
    const float* kf      = (const float*)d_in[3];
    const float* w1      = (const float*)d_in[4];
    const float* gamma1  = (const float*)d_in[5];
    const float* beta1   = (const float*)d_in[6];
    const float* w2      = (const float*)d_in[7];
    const float* gamma2  = (const float*)d_in[8];
    const float* beta2   = (const float*)d_in[9];
    float* out = (float*)d_out;

    float *pP, *ph, *pp1, *pp2, *ps1, *pb1, *ps2, *pb2;
    int* pidx;
    cudaGetSymbolAddress((void**)&pP,   g_P);
    cudaGetSymbolAddress((void**)&ph,   g_h);
    cudaGetSymbolAddress((void**)&pp1,  g_part1);
    cudaGetSymbolAddress((void**)&pp2,  g_part2);
    cudaGetSymbolAddress((void**)&ps1,  g_scale1);
    cudaGetSymbolAddress((void**)&pb1,  g_bias1);
    cudaGetSymbolAddress((void**)&ps2,  g_scale2);
    cudaGetSymbolAddress((void**)&pb2,  g_bias2);
    cudaGetSymbolAddress((void**)&pidx, g_idx);

    const float invN = 1.0f / (float)(B_ * N_);

    // grid binning for pruned 1-NN (32^3)
    zero_kernel<<<256, 256>>>();
    hist_kernel<<<(B_ * (M_ + N_)) / 256, 256>>>(unknown, known);
    scan_kernel<<<4, 1024>>>();
    scatter_kernel<<<(B_ * (M_ + N_)) / 256, 256>>>(unknown, known);

    // 1-NN (bids 0..511) + K2 P_t-GEMM (bids 512..1023) in one launch
    fused_nn_k2_kernel<<<1024, 256>>>(w1, kf, pP);

    // h = w1[:, 256:] @ unknow_feats + gather(P_t, idx); stats1
    gemm_kernel<C1_, true, false, true, false, H1_>
        <<<dim3(N_ / 128, H1_ / 128, B_), 256>>>(
            w1, 384, C2_, uf, N_, pP, pidx, nullptr, nullptr, ph, pp1);

    fin_kernel<H1_><<<H1_, 128>>>(pp1, gamma1, beta1, ps1, pb1, invN);

    // out_pre = w2 @ relu(bn1(h)); stats2
    gemm_kernel<H1_, false, true, true, false, H2_>
        <<<dim3(N_ / 128, H2_ / 128, B_), 256>>>(
            w2, 256, 0, ph, N_, nullptr, nullptr, ps1, pb1, out, pp2);

    fin_kernel<H2_><<<H2_, 128>>>(pp2, gamma2, beta2, ps2, pb2, invN);

    bnfin_kernel<<<dim3(N_ / 1024, B_ * H2_), 256>>>(out, ps2, pb2);
}

// round 14
// speedup vs baseline: 3.3896x; 1.0710x over previous
#include <cuda_runtime.h>
#include <cstdint>

// ---------------------------------------------------------------------------
// Problem constants
// ---------------------------------------------------------------------------
#define B_   2
#define N_   65536
#define M_   16384
#define C1_  128
#define C2_  256
#define H1_  256
#define H2_  128
#define NT_  512
#define EPS_ 1e-5f
#define CELLS 32768          // 32^3 grid per batch, h = 0.25

// ---------------------------------------------------------------------------
// Scratch (device globals -- no allocation allowed)
// ---------------------------------------------------------------------------
__device__ int    g_idx[B_ * N_];
__device__ float  g_P[(size_t)B_ * M_ * H1_];      // TRANSPOSED: [b][m][o]
__device__ float  g_h[(size_t)B_ * H1_ * N_];
__device__ float  g_part1[(size_t)B_ * H1_ * NT_ * 2];
__device__ float  g_part2[(size_t)B_ * H2_ * NT_ * 2];
__device__ float  g_scale1[H1_], g_bias1[H1_];
__device__ float  g_scale2[H2_], g_bias2[H2_];

// grid-NN scratch
__device__ int    g_kcnt[B_ * CELLS], g_kstart[B_ * CELLS], g_kcur[B_ * CELLS];
__device__ int    g_qcnt[B_ * CELLS], g_qstart[B_ * CELLS], g_qcur[B_ * CELLS];
__device__ int    g_kcell[B_ * M_],  g_qcell[B_ * N_];
__device__ __align__(16) float4 g_ksort[B_ * M_];
__device__ __align__(16) float4 g_qsort[B_ * N_];
__device__ int    g_korig[B_ * M_], g_qorig[B_ * N_];

// ---------------------------------------------------------------------------
// helpers
// ---------------------------------------------------------------------------
__device__ __forceinline__ uint32_t cvt_tf32(float f) {
    uint32_t u;
    asm("cvt.rna.tf32.f32 %0, %1;" : "=r"(u) : "f"(f));
    return u;
}
__device__ __forceinline__ void mma_tf32(float* c, const uint32_t* a,
                                         uint32_t b0, uint32_t b1) {
    asm volatile(
        "mma.sync.aligned.m16n8k8.row.col.f32.tf32.tf32.f32 "
        "{%0,%1,%2,%3}, {%4,%5,%6,%7}, {%8,%9}, {%0,%1,%2,%3};\n"
        : "+f"(c[0]), "+f"(c[1]), "+f"(c[2]), "+f"(c[3])
        : "r"(a[0]), "r"(a[1]), "r"(a[2]), "r"(a[3]), "r"(b0), "r"(b1));
}
__device__ __forceinline__ int cellof(float v) {
    int c = __float2int_rd((v + 4.0f) * 4.0f);
    return min(31, max(0, c));
}

// ---------------------------------------------------------------------------
// Binning: zero counters -> histogram -> scan -> scatter  (round-10 exact)
// ---------------------------------------------------------------------------
__global__ void zero_kernel() {
    int i = blockIdx.x * 256 + threadIdx.x;
    if (i < B_ * CELLS) { g_kcnt[i] = 0; g_qcnt[i] = 0; }
}

__global__ void hist_kernel(const float* __restrict__ unknown,
                            const float* __restrict__ known) {
    int j = blockIdx.x * 256 + threadIdx.x;
    if (j < B_ * M_) {
        float x = known[3 * j], y = known[3 * j + 1], z = known[3 * j + 2];
        int cell = (cellof(z) * 32 + cellof(y)) * 32 + cellof(x);
        g_kcell[j] = cell;
        atomicAdd(&g_kcnt[(j / M_) * CELLS + cell], 1);
    } else {
        int q = j - B_ * M_;
        if (q < B_ * N_) {
            float x = unknown[3 * q], y = unknown[3 * q + 1], z = unknown[3 * q + 2];
            int cell = (cellof(z) * 32 + cellof(y)) * 32 + cellof(x);
            g_qcell[q] = cell;
            atomicAdd(&g_qcnt[(q / N_) * CELLS + cell], 1);
        }
    }
}

__global__ void __launch_bounds__(1024) scan_kernel() {
    const int w = blockIdx.x;
    int* cnt;  int* start;  int* cur;
    if (w < 2) { cnt = g_kcnt + w * CELLS; start = g_kstart + w * CELLS; cur = g_kcur + w * CELLS; }
    else { int b = w - 2; cnt = g_qcnt + b * CELLS; start = g_qstart + b * CELLS; cur = g_qcur + b * CELLS; }
    const int t = threadIdx.x;
    int loc[32]; int s = 0;
#pragma unroll
    for (int i = 0; i < 32; i++) { loc[i] = s; s += cnt[t * 32 + i]; }
    const int lane = t & 31, wid = t >> 5;
    int v = s;
#pragma unroll
    for (int off = 1; off < 32; off <<= 1) {
        int n = __shfl_up_sync(0xffffffffu, v, off);
        if (lane >= off) v += n;
    }
    __shared__ int ws[32];
    if (lane == 31) ws[wid] = v;
    __syncthreads();
    if (wid == 0) {
        int x = ws[lane];
#pragma unroll
        for (int off = 1; off < 32; off <<= 1) {
            int n = __shfl_up_sync(0xffffffffu, x, off);
            if (lane >= off) x += n;
        }
        ws[lane] = x;
    }
    __syncthreads();
    int base = v - s + (wid > 0 ? ws[wid - 1] : 0);
#pragma unroll
    for (int i = 0; i < 32; i++) {
        int val = base + loc[i];
        start[t * 32 + i] = val;
        cur[t * 32 + i] = val;
    }
}

__global__ void scatter_kernel(const float* __restrict__ unknown,
                               const float* __restrict__ known) {
    int j = blockIdx.x * 256 + threadIdx.x;
    if (j < B_ * M_) {
        int b = j / M_;
        float x = known[3 * j], y = known[3 * j + 1], z = known[3 * j + 2];
        float k2 = __fadd_rn(__fadd_rn(__fmul_rn(x, x), __fmul_rn(y, y)),
                             __fmul_rn(z, z));
        int pos = atomicAdd(&g_kcur[b * CELLS + g_kcell[j]], 1);
        g_ksort[b * M_ + pos] = make_float4(x, y, z, k2);
        g_korig[b * M_ + pos] = j - b * M_;
    } else {
        int q = j - B_ * M_;
        if (q < B_ * N_) {
            int b = q / N_;
            float x = unknown[3 * q], y = unknown[3 * q + 1], z = unknown[3 * q + 2];
            float u2 = __fadd_rn(__fadd_rn(__fmul_rn(x, x), __fmul_rn(y, y)),
                                 __fmul_rn(z, z));
            int pos = atomicAdd(&g_qcur[b * CELLS + g_qcell[q]], 1);
            g_qsort[(size_t)b * N_ + pos] = make_float4(x, y, z, u2);
            g_qorig[(size_t)b * N_ + pos] = q - b * N_;
        }
    }
}

// ---------------------------------------------------------------------------
// Grid-pruned exact 1-NN, thread-per-query (round-10 body VERBATIM).
// STANDALONE kernel, zero smem, low regs -> high occupancy for latency hiding.
// d per candidate uses the EXACT reference chain:
//   dot = fmaf(uz,kz, fmaf(uy,ky, ux*kx));  d = fadd(fmaf(-2,dot,u2), k2)
// Selection: (min d, then min ORIGINAL index among bitwise-equal d) ==
// reference's sequential first strict-< min (order-independent).
// Ring stop: unexamined points (Chebyshev >= r) have true dist^2 >=
// ((r-1)*0.25)^2; 4e-3 margin covers fp32 error of the d chain.
// ---------------------------------------------------------------------------
__global__ void __launch_bounds__(256) nn_kernel() {
    const int gq = blockIdx.x * 256 + threadIdx.x;
    const int b = gq / N_;
    const float4 q = g_qsort[gq];
    const int oq = g_qorig[gq];
    const int qx = cellof(q.x), qy = cellof(q.y), qz = cellof(q.z);
    float bd = 3.4e38f; int bi = 0;
    const float4* kp = g_ksort + (size_t)b * M_;
    const int*    ko = g_korig + (size_t)b * M_;
    const int*    st = g_kstart + b * CELLS;
    const int*    ct = g_kcnt + b * CELLS;

    for (int r = 0; r <= 31; r++) {
        if (r > 0) {
            float rr = (float)(r - 1) * 0.25f;
            if (bd + 4e-3f <= rr * rr) break;
        }
        int zlo = max(qz - r, 0), zhi = min(qz + r, 31);
        for (int cz = zlo; cz <= zhi; cz++) {
            int adz = (cz > qz) ? (cz - qz) : (qz - cz);
            int ylo = max(qy - r, 0), yhi = min(qy + r, 31);
            for (int cy = ylo; cy <= yhi; cy++) {
                int ady = (cy > qy) ? (cy - qy) : (qy - cy);
                int xlo, xhi, xstep;
                if (adz == r || ady == r) {
                    xlo = max(qx - r, 0); xhi = min(qx + r, 31); xstep = 1;
                } else {
                    xlo = qx - r; xhi = qx + r; xstep = 2 * r;   // r >= 1 here
                }
                for (int cx = xlo; cx <= xhi; cx += xstep) {
                    if ((unsigned)cx > 31u) continue;
                    int cell = (cz * 32 + cy) * 32 + cx;
                    int s = st[cell], e = s + ct[cell];
                    for (int jj = s; jj < e; jj++) {
                        float4 k4 = kp[jj];
                        float dot = __fmul_rn(q.x, k4.x);
                        dot = fmaf(q.y, k4.y, dot);
                        dot = fmaf(q.z, k4.z, dot);
                        float d = __fadd_rn(fmaf(-2.0f, dot, q.w), k4.w);
                        int o = ko[jj];
                        if (d < bd) { bd = d; bi = o; }
                        else if (d == bd && o < bi) { bi = o; }
                    }
                }
            }
        }
    }
    g_idx[(size_t)b * N_ + oq] = bi;
}

// ---------------------------------------------------------------------------
// Tensor-core (tf32 mma.sync) fused GEMM (round-10 body, standalone only).
// ---------------------------------------------------------------------------
template <int KDIM, bool GATHER, bool BN, bool STATS, bool TRANSOUT, int MTOT>
__global__ void __launch_bounds__(256, 2) gemm_kernel(
    const float* __restrict__ W, int ldw, int woff,
    const float* __restrict__ X, int N,
    const float* __restrict__ P,
    const int*   __restrict__ idx,
    const float* __restrict__ bsc,
    const float* __restrict__ bbi,
    float* __restrict__ Y,
    float* __restrict__ part)
{
    __shared__ __align__(16) uint32_t SH[16384];
    __shared__ int idbuf[128];

    const int b   = blockIdx.z;
    const int ob0 = blockIdx.y * 128;
    const int ib0 = blockIdx.x * 128;
    const int nbx = gridDim.x;
    const int bx  = blockIdx.x;
    const int t   = threadIdx.x;
    const int lane = t & 31, wid = t >> 5;
    const int wo = wid >> 1, wn = wid & 1;
    const int gid = lane >> 2, tig = lane & 3;

    const float* Wp = W + woff;
    const float* Xb = X + (size_t)b * KDIM * N;

    float acc[2][8][4];
#pragma unroll
    for (int m = 0; m < 2; m++)
#pragma unroll
        for (int n = 0; n < 8; n++)
#pragma unroll
            for (int e = 0; e < 4; e++) acc[m][n][e] = 0.f;

    const int w_o   = t >> 1;
    const int w_kq0 = (t & 1) * 16;
    const int w_mt  = w_o >> 4, w_gid = w_o & 7, w_hi = (w_o >> 3) & 1;

    const int x_k   = t >> 3;
    const int x_i0  = (t & 7) * 16;
    const int x_s   = x_k >> 3;
    const int x_tig = x_k & 3, x_hi = (x_k >> 2) & 1;

    constexpr int NKT = KDIM / 32;
    int buf = 0;
    for (int kt = 0; kt < NKT; ++kt) {
        const int k0 = kt * 32;
        uint32_t* Ab = SH + buf * 4096;
        uint32_t* Bb = SH + 8192 + buf * 4096;

        {
            const float* wr = Wp + (size_t)(ob0 + w_o) * ldw + k0 + w_kq0;
#pragma unroll
            for (int j = 0; j < 4; j++) {
                float4 v = *(const float4*)(wr + j * 4);
                uint32_t q[4] = {cvt_tf32(v.x), cvt_tf32(v.y), cvt_tf32(v.z), cvt_tf32(v.w)};
#pragma unroll
                for (int e = 0; e < 4; e++) {
                    int kk = w_kq0 + j * 4 + e;
                    int s = kk >> 3, c = kk & 7;
                    Ab[(((s * 8 + w_mt) * 32 + w_gid * 4 + (c & 3)) << 2)
                       + w_hi + ((c >> 2) << 1)] = q[e];
                }
            }
        }
        {
            const float* xr = Xb + (size_t)(k0 + x_k) * N + ib0 + x_i0;
            float bs = 0.f, bb = 0.f;
            if (BN) { bs = bsc[k0 + x_k]; bb = bbi[k0 + x_k]; }
#pragma unroll
            for (int j = 0; j < 4; j++) {
                float4 v = *(const float4*)(xr + j * 4);
                if (BN) {
                    v.x = fmaxf(fmaf(v.x, bs, bb), 0.f);
                    v.y = fmaxf(fmaf(v.y, bs, bb), 0.f);
                    v.z = fmaxf(fmaf(v.z, bs, bb), 0.f);
                    v.w = fmaxf(fmaf(v.w, bs, bb), 0.f);
                }
                uint32_t q[4] = {cvt_tf32(v.x), cvt_tf32(v.y), cvt_tf32(v.z), cvt_tf32(v.w)};
#pragma unroll
                for (int e = 0; e < 4; e++) {
                    int i = x_i0 + j * 4 + e;
                    int nt = i >> 3, gg = i & 7;
                    Bb[(((x_s * 8 + (nt >> 1)) * 32 + gg * 4 + x_tig) << 2)
                       + (nt & 1) * 2 + x_hi] = q[e];
                }
            }
        }
        __syncthreads();
#pragma unroll
        for (int s = 0; s < 4; s++) {
            uint4 af[2];
            af[0] = *(const uint4*)&Ab[((s * 8 + wo * 2 + 0) * 32 + lane) << 2];
            af[1] = *(const uint4*)&Ab[((s * 8 + wo * 2 + 1) * 32 + lane) << 2];
            uint4 bf[4];
#pragma unroll
            for (int p = 0; p < 4; p++)
                bf[p] = *(const uint4*)&Bb[((s * 8 + wn * 4 + p) * 32 + lane) << 2];
#pragma unroll
            for (int m = 0; m < 2; m++)
#pragma unroll
                for (int p = 0; p < 4; p++) {
                    mma_tf32(acc[m][2 * p],     (const uint32_t*)&af[m], bf[p].x, bf[p].y);
                    mma_tf32(acc[m][2 * p + 1], (const uint32_t*)&af[m], bf[p].z, bf[p].w);
                }
        }
        buf ^= 1;
    }

    const int o_base = ob0 + wo * 32;
    const int i_base = ib0 + wn * 64;

    if (GATHER) {
        __syncthreads();
        if (t < 128) idbuf[t] = idx[(size_t)b * N + ib0 + t];
        __syncthreads();
        float* G = (float*)SH;
#pragma unroll
        for (int j = 0; j < 16; j++) {
            int lin = t + j * 256;
            int r = lin >> 5, c4 = (lin & 31) << 2;
            const float* src = P + ((size_t)b * M_ + idbuf[r]) * MTOT + ob0 + c4;
            *(float4*)&G[r * 128 + c4] = *(const float4*)src;
        }
        __syncthreads();
        const int i0l = wn * 64 + tig * 2;
        const int o0l = wo * 32 + gid;
#pragma unroll
        for (int m = 0; m < 2; m++) {
            int oo = o0l + m * 16;
#pragma unroll
            for (int n = 0; n < 8; n++) {
                int ii = i0l + n * 8;
                acc[m][n][0] += G[ii * 128 + oo];
                acc[m][n][1] += G[(ii + 1) * 128 + oo];
                acc[m][n][2] += G[ii * 128 + oo + 8];
                acc[m][n][3] += G[(ii + 1) * 128 + oo + 8];
            }
        }
    }

    if (TRANSOUT) {
#pragma unroll
        for (int m = 0; m < 2; m++)
#pragma unroll
            for (int n = 0; n < 8; n++) {
                int i_ = i_base + n * 8 + tig * 2;
                int o_ = o_base + m * 16 + gid;
                float* Yr = Y + ((size_t)b * N + i_) * MTOT;
                Yr[o_]            = acc[m][n][0];
                Yr[MTOT + o_]     = acc[m][n][1];
                Yr[o_ + 8]        = acc[m][n][2];
                Yr[MTOT + o_ + 8] = acc[m][n][3];
            }
    } else {
#pragma unroll
        for (int m = 0; m < 2; m++) {
            float* Y0 = Y + ((size_t)b * MTOT + o_base + m * 16 + gid) * N + i_base + tig * 2;
            float* Y8 = Y0 + (size_t)8 * N;
#pragma unroll
            for (int n = 0; n < 8; n++) {
                *(float2*)(Y0 + n * 8) = make_float2(acc[m][n][0], acc[m][n][1]);
                *(float2*)(Y8 + n * 8) = make_float2(acc[m][n][2], acc[m][n][3]);
            }
        }
    }

    if (STATS) {
        float s1[2][2], s2[2][2];
#pragma unroll
        for (int m = 0; m < 2; m++) {
            float a0 = 0.f, q0 = 0.f, a1 = 0.f, q1 = 0.f;
#pragma unroll
            for (int n = 0; n < 8; n++) {
                a0 += acc[m][n][0]; q0 = fmaf(acc[m][n][0], acc[m][n][0], q0);
                a0 += acc[m][n][1]; q0 = fmaf(acc[m][n][1], acc[m][n][1], q0);
                a1 += acc[m][n][2]; q1 = fmaf(acc[m][n][2], acc[m][n][2], q1);
                a1 += acc[m][n][3]; q1 = fmaf(acc[m][n][3], acc[m][n][3], q1);
            }
            s1[m][0] = a0; s2[m][0] = q0; s1[m][1] = a1; s2[m][1] = q1;
        }
#pragma unroll
        for (int m = 0; m < 2; m++)
#pragma unroll
            for (int h = 0; h < 2; h++) {
#pragma unroll
                for (int off = 1; off <= 2; off <<= 1) {
                    s1[m][h] += __shfl_xor_sync(0xffffffffu, s1[m][h], off);
                    s2[m][h] += __shfl_xor_sync(0xffffffffu, s2[m][h], off);
                }
            }
        float* sb1 = (float*)SH;
        float* sb2 = sb1 + 256;
        __syncthreads();
        if (tig == 0) {
#pragma unroll
            for (int m = 0; m < 2; m++)
#pragma unroll
                for (int h = 0; h < 2; h++) {
                    int ol = wo * 32 + m * 16 + h * 8 + gid;
                    sb1[wn * 128 + ol] = s1[m][h];
                    sb2[wn * 128 + ol] = s2[m][h];
                }
        }
        __syncthreads();
        if (t < 128) {
            float tot = sb1[t] + sb1[128 + t];
            part[(((size_t)b * MTOT + ob0 + t) * nbx + bx) * 2 + 0] = tot;
        } else {
            int o = t - 128;
            float tot = sb2[o] + sb2[128 + o];
            part[(((size_t)b * MTOT + ob0 + o) * nbx + bx) * 2 + 1] = tot;
        }
    }
}

// ---------------------------------------------------------------------------
// Finalize BN stats: one block per channel
// ---------------------------------------------------------------------------
template <int MTOT>
__global__ void __launch_bounds__(128) fin_kernel(
    const float* __restrict__ part,
    const float* __restrict__ gamma, const float* __restrict__ beta,
    float* __restrict__ sc, float* __restrict__ bi, float invN)
{
    const int o = blockIdx.x;
    const int t = threadIdx.x;
    float s1 = 0.f, s2 = 0.f;
    for (int b = 0; b < B_; b++) {
        const float* p = part + ((size_t)b * MTOT + o) * NT_ * 2;
        for (int q = t; q < NT_; q += 128) {
            s1 += p[q * 2 + 0];
            s2 += p[q * 2 + 1];
        }
    }
#pragma unroll
    for (int off = 16; off; off >>= 1) {
        s1 += __shfl_down_sync(0xffffffffu, s1, off);
        s2 += __shfl_down_sync(0xffffffffu, s2, off);
    }
    __shared__ float r1[4], r2[4];
    if ((t & 31) == 0) { r1[t >> 5] = s1; r2[t >> 5] = s2; }
    __syncthreads();
    if (t == 0) {
        s1 = r1[0] + r1[1] + r1[2] + r1[3];
        s2 = r2[0] + r2[1] + r2[2] + r2[3];
        float mean = s1 * invN;
        float var  = s2 * invN - mean * mean;
        float rstd = rsqrtf(var + EPS_);
        float s    = gamma[o] * rstd;
        sc[o] = s;
        bi[o] = beta[o] - mean * s;
    }
}

// ---------------------------------------------------------------------------
// Final elementwise BN+ReLU in-place on d_out
// ---------------------------------------------------------------------------
__global__ void __launch_bounds__(256) bnfin_kernel(
    float* __restrict__ Y, const float* __restrict__ sc, const float* __restrict__ bi)
{
    int row = blockIdx.y;
    int ch  = row & (H2_ - 1);
    size_t base = (size_t)row * N_;
    int i = (blockIdx.x * 256 + threadIdx.x) * 4;
    float4 v = *(float4*)(Y + base + i);
    float s = sc[ch], b = bi[ch];
    v.x = fmaxf(fmaf(v.x, s, b), 0.f);
    v.y = fmaxf(fmaf(v.y, s, b), 0.f);
    v.z = fmaxf(fmaf(v.z, s, b), 0.f);
    v.w = fmaxf(fmaf(v.w, s, b), 0.f);
    *(float4*)(Y + base + i) = v;
}

// ---------------------------------------------------------------------------
// Launch
// ---------------------------------------------------------------------------
extern "C" void kernel_launch(void* const* d_in, const int* in_sizes, int n_in,
                              void* d_out, int out_size)
{
    const float* unknown = (const float*)d_in[0];
    const float* known   = (const float*)d_in[1];
    const float* uf      = (const float*)d_in[2];
    const float* kf      = (const float*)d_in[3];
    const float* w1      = (const float*)d_in[4];
    const float* gamma1  = (const float*)d_in[5];
    const float* beta1   = (const float*)d_in[6];
    const float* w2      = (const float*)d_in[7];
    const float* gamma2  = (const float*)d_in[8];
    const float* beta2   = (const float*)d_in[9];
    float* out = (float*)d_out;

    float *pP, *ph, *pp1, *pp2, *ps1, *pb1, *ps2, *pb2;
    int* pidx;
    cudaGetSymbolAddress((void**)&pP,   g_P);
    cudaGetSymbolAddress((void**)&ph,   g_h);
    cudaGetSymbolAddress((void**)&pp1,  g_part1);
    cudaGetSymbolAddress((void**)&pp2,  g_part2);
    cudaGetSymbolAddress((void**)&ps1,  g_scale1);
    cudaGetSymbolAddress((void**)&pb1,  g_bias1);
    cudaGetSymbolAddress((void**)&ps2,  g_scale2);
    cudaGetSymbolAddress((void**)&pb2,  g_bias2);
    cudaGetSymbolAddress((void**)&pidx, g_idx);

    const float invN = 1.0f / (float)(B_ * N_);

    // grid binning for pruned 1-NN (32^3)
    zero_kernel<<<256, 256>>>();
    hist_kernel<<<(B_ * (M_ + N_)) / 256, 256>>>(unknown, known);
    scan_kernel<<<4, 1024>>>();
    scatter_kernel<<<(B_ * (M_ + N_)) / 256, 256>>>(unknown, known);

    // 1-NN standalone: zero smem, low regs -> high occupancy
    nn_kernel<<<512, 256>>>();

    // K2: P_t[b][m][o] = (w1[:, :256] @ kf)^T
    gemm_kernel<C2_, false, false, false, true, H1_>
        <<<dim3(M_ / 128, H1_ / 128, B_), 256>>>(
            w1, 384, 0, kf, M_, nullptr, nullptr, nullptr, nullptr, pP, nullptr);

    // h = w1[:, 256:] @ unknow_feats + gather(P_t, idx); stats1
    gemm_kernel<C1_, true, false, true, false, H1_>
        <<<dim3(N_ / 128, H1_ / 128, B_), 256>>>(
            w1, 384, C2_, uf, N_, pP, pidx, nullptr, nullptr, ph, pp1);

    fin_kernel<H1_><<<H1_, 128>>>(pp1, gamma1, beta1, ps1, pb1, invN);

    // out_pre = w2 @ relu(bn1(h)); stats2
    gemm_kernel<H1_, false, true, true, false, H2_>
        <<<dim3(N_ / 128, H2_ / 128, B_), 256>>>(
            w2, 256, 0, ph, N_, nullptr, nullptr, ps1, pb1, out, pp2);

    fin_kernel<H2_><<<H2_, 128>>>(pp2, gamma2, beta2, ps2, pb2, invN);

    bnfin_kernel<<<dim3(N_ / 1024, B_ * H2_), 256>>>(out, ps2, pb2);
}

// round 15
// speedup vs baseline: 3.7205x; 1.0976x over previous
#include <cuda_runtime.h>
#include <cstdint>

// ---------------------------------------------------------------------------
// Problem constants
// ---------------------------------------------------------------------------
#define B_   2
#define N_   65536
#define M_   16384
#define C1_  128
#define C2_  256
#define H1_  256
#define H2_  128
#define NT_  512
#define EPS_ 1e-5f
#define CELLS 32768          // 32^3 grid per batch, h = 0.25

// ---------------------------------------------------------------------------
// Scratch (device globals -- no allocation allowed)
// ---------------------------------------------------------------------------
__device__ int    g_idx[B_ * N_];
__device__ float  g_P[(size_t)B_ * M_ * H1_];      // TRANSPOSED: [b][m][o]
__device__ float  g_h[(size_t)B_ * H1_ * N_];
__device__ float  g_part1[(size_t)B_ * H1_ * NT_ * 2];
__device__ float  g_part2[(size_t)B_ * H2_ * NT_ * 2];
__device__ float  g_scale1[H1_], g_bias1[H1_];
__device__ float  g_scale2[H2_], g_bias2[H2_];

// grid-NN scratch
__device__ int    g_kcnt[B_ * CELLS], g_kstart[B_ * CELLS], g_kcur[B_ * CELLS];
__device__ int    g_qcnt[B_ * CELLS], g_qstart[B_ * CELLS], g_qcur[B_ * CELLS];
__device__ int    g_kcell[B_ * M_],  g_qcell[B_ * N_];
__device__ __align__(16) float4 g_ksort[B_ * M_];
__device__ __align__(16) float4 g_qsort[B_ * N_];
__device__ int    g_korig[B_ * M_], g_qorig[B_ * N_];

// ---------------------------------------------------------------------------
// helpers
// ---------------------------------------------------------------------------
__device__ __forceinline__ uint32_t cvt_tf32(float f) {
    uint32_t u;
    asm("cvt.rna.tf32.f32 %0, %1;" : "=r"(u) : "f"(f));
    return u;
}
__device__ __forceinline__ void mma_tf32(float* c, const uint32_t* a,
                                         uint32_t b0, uint32_t b1) {
    asm volatile(
        "mma.sync.aligned.m16n8k8.row.col.f32.tf32.tf32.f32 "
        "{%0,%1,%2,%3}, {%4,%5,%6,%7}, {%8,%9}, {%0,%1,%2,%3};\n"
        : "+f"(c[0]), "+f"(c[1]), "+f"(c[2]), "+f"(c[3])
        : "r"(a[0]), "r"(a[1]), "r"(a[2]), "r"(a[3]), "r"(b0), "r"(b1));
}
__device__ __forceinline__ int cellof(float v) {
    int c = __float2int_rd((v + 4.0f) * 4.0f);
    return min(31, max(0, c));
}
// per-axis distance from q to cell slab [lo, hi); clamped cells extend to inf
__device__ __forceinline__ float axdist(float qv, int c) {
    float lo = -4.0f + 0.25f * (float)c;
    float hi = lo + 0.25f;
    float d = fmaxf(lo - qv, qv - hi);
    if (c == 0)  d = fminf(d, qv - hi);   // lower side unbounded
    if (c == 31) d = fmaxf(lo - qv, 0.f); // upper side unbounded (keep lo side)
    return fmaxf(d, 0.f);
}

// ---------------------------------------------------------------------------
// Binning: zero counters -> histogram -> scan -> scatter  (round-10 exact)
// ---------------------------------------------------------------------------
__global__ void zero_kernel() {
    int i = blockIdx.x * 256 + threadIdx.x;
    if (i < B_ * CELLS) { g_kcnt[i] = 0; g_qcnt[i] = 0; }
}

__global__ void hist_kernel(const float* __restrict__ unknown,
                            const float* __restrict__ known) {
    int j = blockIdx.x * 256 + threadIdx.x;
    if (j < B_ * M_) {
        float x = known[3 * j], y = known[3 * j + 1], z = known[3 * j + 2];
        int cell = (cellof(z) * 32 + cellof(y)) * 32 + cellof(x);
        g_kcell[j] = cell;
        atomicAdd(&g_kcnt[(j / M_) * CELLS + cell], 1);
    } else {
        int q = j - B_ * M_;
        if (q < B_ * N_) {
            float x = unknown[3 * q], y = unknown[3 * q + 1], z = unknown[3 * q + 2];
            int cell = (cellof(z) * 32 + cellof(y)) * 32 + cellof(x);
            g_qcell[q] = cell;
            atomicAdd(&g_qcnt[(q / N_) * CELLS + cell], 1);
        }
    }
}

__global__ void __launch_bounds__(1024) scan_kernel() {
    const int w = blockIdx.x;
    int* cnt;  int* start;  int* cur;
    if (w < 2) { cnt = g_kcnt + w * CELLS; start = g_kstart + w * CELLS; cur = g_kcur + w * CELLS; }
    else { int b = w - 2; cnt = g_qcnt + b * CELLS; start = g_qstart + b * CELLS; cur = g_qcur + b * CELLS; }
    const int t = threadIdx.x;
    int loc[32]; int s = 0;
#pragma unroll
    for (int i = 0; i < 32; i++) { loc[i] = s; s += cnt[t * 32 + i]; }
    const int lane = t & 31, wid = t >> 5;
    int v = s;
#pragma unroll
    for (int off = 1; off < 32; off <<= 1) {
        int n = __shfl_up_sync(0xffffffffu, v, off);
        if (lane >= off) v += n;
    }
    __shared__ int ws[32];
    if (lane == 31) ws[wid] = v;
    __syncthreads();
    if (wid == 0) {
        int x = ws[lane];
#pragma unroll
        for (int off = 1; off < 32; off <<= 1) {
            int n = __shfl_up_sync(0xffffffffu, x, off);
            if (lane >= off) x += n;
        }
        ws[lane] = x;
    }
    __syncthreads();
    int base = v - s + (wid > 0 ? ws[wid - 1] : 0);
#pragma unroll
    for (int i = 0; i < 32; i++) {
        int val = base + loc[i];
        start[t * 32 + i] = val;
        cur[t * 32 + i] = val;
    }
}

__global__ void scatter_kernel(const float* __restrict__ unknown,
                               const float* __restrict__ known) {
    int j = blockIdx.x * 256 + threadIdx.x;
    if (j < B_ * M_) {
        int b = j / M_;
        float x = known[3 * j], y = known[3 * j + 1], z = known[3 * j + 2];
        float k2 = __fadd_rn(__fadd_rn(__fmul_rn(x, x), __fmul_rn(y, y)),
                             __fmul_rn(z, z));
        int pos = atomicAdd(&g_kcur[b * CELLS + g_kcell[j]], 1);
        g_ksort[b * M_ + pos] = make_float4(x, y, z, k2);
        g_korig[b * M_ + pos] = j - b * M_;
    } else {
        int q = j - B_ * M_;
        if (q < B_ * N_) {
            int b = q / N_;
            float x = unknown[3 * q], y = unknown[3 * q + 1], z = unknown[3 * q + 2];
            float u2 = __fadd_rn(__fadd_rn(__fmul_rn(x, x), __fmul_rn(y, y)),
                                 __fmul_rn(z, z));
            int pos = atomicAdd(&g_qcur[b * CELLS + g_qcell[q]], 1);
            g_qsort[(size_t)b * N_ + pos] = make_float4(x, y, z, u2);
            g_qorig[(size_t)b * N_ + pos] = q - b * N_;
        }
    }
}

// ---------------------------------------------------------------------------
// Grid-pruned exact 1-NN, thread-per-query (round-10 traversal) + exact
// per-cell lower-bound pruning:
//   mind2(cell) = sum_axis max(lo - q, q - hi, 0)^2   (clamped cells -> inf
//   extension outward, so bound only shrinks -> never wrongly prunes).
// Skip cell if bd + 4e-3 <= mind2: every point there has true d2 >= bd+4e-3,
// so its chain-d > bd strictly (chain error << 4e-3) -> cannot beat or tie.
// Same margin/inequality form as the ring stop (bitwise-validated).
// d per candidate uses the EXACT reference chain:
//   dot = fmaf(uz,kz, fmaf(uy,ky, ux*kx));  d = fadd(fmaf(-2,dot,u2), k2)
// Selection: (min d, then min ORIGINAL index among bitwise-equal d) ==
// reference's sequential first strict-< min (order-independent).
// ---------------------------------------------------------------------------
__global__ void __launch_bounds__(256) nn_kernel() {
    const int gq = blockIdx.x * 256 + threadIdx.x;
    const int b = gq / N_;
    const float4 q = g_qsort[gq];
    const int oq = g_qorig[gq];
    const int qx = cellof(q.x), qy = cellof(q.y), qz = cellof(q.z);
    float bd = 3.4e38f; int bi = 0;
    const float4* kp = g_ksort + (size_t)b * M_;
    const int*    ko = g_korig + (size_t)b * M_;
    const int*    st = g_kstart + b * CELLS;
    const int*    ct = g_kcnt + b * CELLS;

    for (int r = 0; r <= 31; r++) {
        if (r > 0) {
            float rr = (float)(r - 1) * 0.25f;
            if (bd + 4e-3f <= rr * rr) break;
        }
        int zlo = max(qz - r, 0), zhi = min(qz + r, 31);
        for (int cz = zlo; cz <= zhi; cz++) {
            float dz = axdist(q.z, cz);
            float dz2 = dz * dz;
            if (bd + 4e-3f <= dz2) continue;          // whole z-plane pruned
            int adz = (cz > qz) ? (cz - qz) : (qz - cz);
            int ylo = max(qy - r, 0), yhi = min(qy + r, 31);
            for (int cy = ylo; cy <= yhi; cy++) {
                float dy = axdist(q.y, cy);
                float dyz2 = fmaf(dy, dy, dz2);
                if (bd + 4e-3f <= dyz2) continue;     // whole y-row pruned
                int ady = (cy > qy) ? (cy - qy) : (qy - cy);
                int xlo, xhi, xstep;
                if (adz == r || ady == r) {
                    xlo = max(qx - r, 0); xhi = min(qx + r, 31); xstep = 1;
                } else {
                    xlo = qx - r; xhi = qx + r; xstep = 2 * r;   // r >= 1 here
                }
                for (int cx = xlo; cx <= xhi; cx += xstep) {
                    if ((unsigned)cx > 31u) continue;
                    float dx = axdist(q.x, cx);
                    float mind2 = fmaf(dx, dx, dyz2);
                    if (bd + 4e-3f <= mind2) continue; // cell pruned
                    int cell = (cz * 32 + cy) * 32 + cx;
                    int s = st[cell], e = s + ct[cell];
                    for (int jj = s; jj < e; jj++) {
                        float4 k4 = kp[jj];
                        float dot = __fmul_rn(q.x, k4.x);
                        dot = fmaf(q.y, k4.y, dot);
                        dot = fmaf(q.z, k4.z, dot);
                        float d = __fadd_rn(fmaf(-2.0f, dot, q.w), k4.w);
                        int o = ko[jj];
                        if (d < bd) { bd = d; bi = o; }
                        else if (d == bd && o < bi) { bi = o; }
                    }
                }
            }
        }
    }
    g_idx[(size_t)b * N_ + oq] = bi;
}

// ---------------------------------------------------------------------------
// Tensor-core (tf32 mma.sync) fused GEMM (round-10 body, standalone only).
// ---------------------------------------------------------------------------
template <int KDIM, bool GATHER, bool BN, bool STATS, bool TRANSOUT, int MTOT>
__global__ void __launch_bounds__(256, 2) gemm_kernel(
    const float* __restrict__ W, int ldw, int woff,
    const float* __restrict__ X, int N,
    const float* __restrict__ P,
    const int*   __restrict__ idx,
    const float* __restrict__ bsc,
    const float* __restrict__ bbi,
    float* __restrict__ Y,
    float* __restrict__ part)
{
    __shared__ __align__(16) uint32_t SH[16384];
    __shared__ int idbuf[128];

    const int b   = blockIdx.z;
    const int ob0 = blockIdx.y * 128;
    const int ib0 = blockIdx.x * 128;
    const int nbx = gridDim.x;
    const int bx  = blockIdx.x;
    const int t   = threadIdx.x;
    const int lane = t & 31, wid = t >> 5;
    const int wo = wid >> 1, wn = wid & 1;
    const int gid = lane >> 2, tig = lane & 3;

    const float* Wp = W + woff;
    const float* Xb = X + (size_t)b * KDIM * N;

    float acc[2][8][4];
#pragma unroll
    for (int m = 0; m < 2; m++)
#pragma unroll
        for (int n = 0; n < 8; n++)
#pragma unroll
            for (int e = 0; e < 4; e++) acc[m][n][e] = 0.f;

    const int w_o   = t >> 1;
    const int w_kq0 = (t & 1) * 16;
    const int w_mt  = w_o >> 4, w_gid = w_o & 7, w_hi = (w_o >> 3) & 1;

    const int x_k   = t >> 3;
    const int x_i0  = (t & 7) * 16;
    const int x_s   = x_k >> 3;
    const int x_tig = x_k & 3, x_hi = (x_k >> 2) & 1;

    constexpr int NKT = KDIM / 32;
    int buf = 0;
    for (int kt = 0; kt < NKT; ++kt) {
        const int k0 = kt * 32;
        uint32_t* Ab = SH + buf * 4096;
        uint32_t* Bb = SH + 8192 + buf * 4096;

        {
            const float* wr = Wp + (size_t)(ob0 + w_o) * ldw + k0 + w_kq0;
#pragma unroll
            for (int j = 0; j < 4; j++) {
                float4 v = *(const float4*)(wr + j * 4);
                uint32_t q[4] = {cvt_tf32(v.x), cvt_tf32(v.y), cvt_tf32(v.z), cvt_tf32(v.w)};
#pragma unroll
                for (int e = 0; e < 4; e++) {
                    int kk = w_kq0 + j * 4 + e;
                    int s = kk >> 3, c = kk & 7;
                    Ab[(((s * 8 + w_mt) * 32 + w_gid * 4 + (c & 3)) << 2)
                       + w_hi + ((c >> 2) << 1)] = q[e];
                }
            }
        }
        {
            const float* xr = Xb + (size_t)(k0 + x_k) * N + ib0 + x_i0;
            float bs = 0.f, bb = 0.f;
            if (BN) { bs = bsc[k0 + x_k]; bb = bbi[k0 + x_k]; }
#pragma unroll
            for (int j = 0; j < 4; j++) {
                float4 v = *(const float4*)(xr + j * 4);
                if (BN) {
                    v.x = fmaxf(fmaf(v.x, bs, bb), 0.f);
                    v.y = fmaxf(fmaf(v.y, bs, bb), 0.f);
                    v.z = fmaxf(fmaf(v.z, bs, bb), 0.f);
                    v.w = fmaxf(fmaf(v.w, bs, bb), 0.f);
                }
                uint32_t q[4] = {cvt_tf32(v.x), cvt_tf32(v.y), cvt_tf32(v.z), cvt_tf32(v.w)};
#pragma unroll
                for (int e = 0; e < 4; e++) {
                    int i = x_i0 + j * 4 + e;
                    int nt = i >> 3, gg = i & 7;
                    Bb[(((x_s * 8 + (nt >> 1)) * 32 + gg * 4 + x_tig) << 2)
                       + (nt & 1) * 2 + x_hi] = q[e];
                }
            }
        }
        __syncthreads();
#pragma unroll
        for (int s = 0; s < 4; s++) {
            uint4 af[2];
            af[0] = *(const uint4*)&Ab[((s * 8 + wo * 2 + 0) * 32 + lane) << 2];
            af[1] = *(const uint4*)&Ab[((s * 8 + wo * 2 + 1) * 32 + lane) << 2];
            uint4 bf[4];
#pragma unroll
            for (int p = 0; p < 4; p++)
                bf[p] = *(const uint4*)&Bb[((s * 8 + wn * 4 + p) * 32 + lane) << 2];
#pragma unroll
            for (int m = 0; m < 2; m++)
#pragma unroll
                for (int p = 0; p < 4; p++) {
                    mma_tf32(acc[m][2 * p],     (const uint32_t*)&af[m], bf[p].x, bf[p].y);
                    mma_tf32(acc[m][2 * p + 1], (const uint32_t*)&af[m], bf[p].z, bf[p].w);
                }
        }
        buf ^= 1;
    }

    const int o_base = ob0 + wo * 32;
    const int i_base = ib0 + wn * 64;

    if (GATHER) {
        __syncthreads();
        if (t < 128) idbuf[t] = idx[(size_t)b * N + ib0 + t];
        __syncthreads();
        float* G = (float*)SH;
#pragma unroll
        for (int j = 0; j < 16; j++) {
            int lin = t + j * 256;
            int r = lin >> 5, c4 = (lin & 31) << 2;
            const float* src = P + ((size_t)b * M_ + idbuf[r]) * MTOT + ob0 + c4;
            *(float4*)&G[r * 128 + c4] = *(const float4*)src;
        }
        __syncthreads();
        const int i0l = wn * 64 + tig * 2;
        const int o0l = wo * 32 + gid;
#pragma unroll
        for (int m = 0; m < 2; m++) {
            int oo = o0l + m * 16;
#pragma unroll
            for (int n = 0; n < 8; n++) {
                int ii = i0l + n * 8;
                acc[m][n][0] += G[ii * 128 + oo];
                acc[m][n][1] += G[(ii + 1) * 128 + oo];
                acc[m][n][2] += G[ii * 128 + oo + 8];
                acc[m][n][3] += G[(ii + 1) * 128 + oo + 8];
            }
        }
    }

    if (TRANSOUT) {
#pragma unroll
        for (int m = 0; m < 2; m++)
#pragma unroll
            for (int n = 0; n < 8; n++) {
                int i_ = i_base + n * 8 + tig * 2;
                int o_ = o_base + m * 16 + gid;
                float* Yr = Y + ((size_t)b * N + i_) * MTOT;
                Yr[o_]            = acc[m][n][0];
                Yr[MTOT + o_]     = acc[m][n][1];
                Yr[o_ + 8]        = acc[m][n][2];
                Yr[MTOT + o_ + 8] = acc[m][n][3];
            }
    } else {
#pragma unroll
        for (int m = 0; m < 2; m++) {
            float* Y0 = Y + ((size_t)b * MTOT + o_base + m * 16 + gid) * N + i_base + tig * 2;
            float* Y8 = Y0 + (size_t)8 * N;
#pragma unroll
            for (int n = 0; n < 8; n++) {
                *(float2*)(Y0 + n * 8) = make_float2(acc[m][n][0], acc[m][n][1]);
                *(float2*)(Y8 + n * 8) = make_float2(acc[m][n][2], acc[m][n][3]);
            }
        }
    }

    if (STATS) {
        float s1[2][2], s2[2][2];
#pragma unroll
        for (int m = 0; m < 2; m++) {
            float a0 = 0.f, q0 = 0.f, a1 = 0.f, q1 = 0.f;
#pragma unroll
            for (int n = 0; n < 8; n++) {
                a0 += acc[m][n][0]; q0 = fmaf(acc[m][n][0], acc[m][n][0], q0);
                a0 += acc[m][n][1]; q0 = fmaf(acc[m][n][1], acc[m][n][1], q0);
                a1 += acc[m][n][2]; q1 = fmaf(acc[m][n][2], acc[m][n][2], q1);
                a1 += acc[m][n][3]; q1 = fmaf(acc[m][n][3], acc[m][n][3], q1);
            }
            s1[m][0] = a0; s2[m][0] = q0; s1[m][1] = a1; s2[m][1] = q1;
        }
#pragma unroll
        for (int m = 0; m < 2; m++)
#pragma unroll
            for (int h = 0; h < 2; h++) {
#pragma unroll
                for (int off = 1; off <= 2; off <<= 1) {
                    s1[m][h] += __shfl_xor_sync(0xffffffffu, s1[m][h], off);
                    s2[m][h] += __shfl_xor_sync(0xffffffffu, s2[m][h], off);
                }
            }
        float* sb1 = (float*)SH;
        float* sb2 = sb1 + 256;
        __syncthreads();
        if (tig == 0) {
#pragma unroll
            for (int m = 0; m < 2; m++)
#pragma unroll
                for (int h = 0; h < 2; h++) {
                    int ol = wo * 32 + m * 16 + h * 8 + gid;
                    sb1[wn * 128 + ol] = s1[m][h];
                    sb2[wn * 128 + ol] = s2[m][h];
                }
        }
        __syncthreads();
        if (t < 128) {
            float tot = sb1[t] + sb1[128 + t];
            part[(((size_t)b * MTOT + ob0 + t) * nbx + bx) * 2 + 0] = tot;
        } else {
            int o = t - 128;
            float tot = sb2[o] + sb2[128 + o];
            part[(((size_t)b * MTOT + ob0 + o) * nbx + bx) * 2 + 1] = tot;
        }
    }
}

// ---------------------------------------------------------------------------
// Finalize BN stats: one block per channel
// ---------------------------------------------------------------------------
template <int MTOT>
__global__ void __launch_bounds__(128) fin_kernel(
    const float* __restrict__ part,
    const float* __restrict__ gamma, const float* __restrict__ beta,
    float* __restrict__ sc, float* __restrict__ bi, float invN)
{
    const int o = blockIdx.x;
    const int t = threadIdx.x;
    float s1 = 0.f, s2 = 0.f;
    for (int b = 0; b < B_; b++) {
        const float* p = part + ((size_t)b * MTOT + o) * NT_ * 2;
        for (int q = t; q < NT_; q += 128) {
            s1 += p[q * 2 + 0];
            s2 += p[q * 2 + 1];
        }
    }
#pragma unroll
    for (int off = 16; off; off >>= 1) {
        s1 += __shfl_down_sync(0xffffffffu, s1, off);
        s2 += __shfl_down_sync(0xffffffffu, s2, off);
    }
    __shared__ float r1[4], r2[4];
    if ((t & 31) == 0) { r1[t >> 5] = s1; r2[t >> 5] = s2; }
    __syncthreads();
    if (t == 0) {
        s1 = r1[0] + r1[1] + r1[2] + r1[3];
        s2 = r2[0] + r2[1] + r2[2] + r2[3];
        float mean = s1 * invN;
        float var  = s2 * invN - mean * mean;
        float rstd = rsqrtf(var + EPS_);
        float s    = gamma[o] * rstd;
        sc[o] = s;
        bi[o] = beta[o] - mean * s;
    }
}

// ---------------------------------------------------------------------------
// Final elementwise BN+ReLU in-place on d_out
// ---------------------------------------------------------------------------
__global__ void __launch_bounds__(256) bnfin_kernel(
    float* __restrict__ Y, const float* __restrict__ sc, const float* __restrict__ bi)
{
    int row = blockIdx.y;
    int ch  = row & (H2_ - 1);
    size_t base = (size_t)row * N_;
    int i = (blockIdx.x * 256 + threadIdx.x) * 4;
    float4 v = *(float4*)(Y + base + i);
    float s = sc[ch], b = bi[ch];
    v.x = fmaxf(fmaf(v.x, s, b), 0.f);
    v.y = fmaxf(fmaf(v.y, s, b), 0.f);
    v.z = fmaxf(fmaf(v.z, s, b), 0.f);
    v.w = fmaxf(fmaf(v.w, s, b), 0.f);
    *(float4*)(Y + base + i) = v;
}

// ---------------------------------------------------------------------------
// Launch
// ---------------------------------------------------------------------------
extern "C" void kernel_launch(void* const* d_in, const int* in_sizes, int n_in,
                              void* d_out, int out_size)
{
    const float* unknown = (const float*)d_in[0];
    const float* known   = (const float*)d_in[1];
    const float* uf      = (const float*)d_in[2];
    const float* kf      = (const float*)d_in[3];
    const float* w1      = (const float*)d_in[4];
    const float* gamma1  = (const float*)d_in[5];
    const float* beta1   = (const float*)d_in[6];
    const float* w2      = (const float*)d_in[7];
    const float* gamma2  = (const float*)d_in[8];
    const float* beta2   = (const float*)d_in[9];
    float* out = (float*)d_out;

    float *pP, *ph, *pp1, *pp2, *ps1, *pb1, *ps2, *pb2;
    int* pidx;
    cudaGetSymbolAddress((void**)&pP,   g_P);
    cudaGetSymbolAddress((void**)&ph,   g_h);
    cudaGetSymbolAddress((void**)&pp1,  g_part1);
    cudaGetSymbolAddress((void**)&pp2,  g_part2);
    cudaGetSymbolAddress((void**)&ps1,  g_scale1);
    cudaGetSymbolAddress((void**)&pb1,  g_bias1);
    cudaGetSymbolAddress((void**)&ps2,  g_scale2);
    cudaGetSymbolAddress((void**)&pb2,  g_bias2);
    cudaGetSymbolAddress((void**)&pidx, g_idx);

    const float invN = 1.0f / (float)(B_ * N_);

    // grid binning for pruned 1-NN (32^3)
    zero_kernel<<<256, 256>>>();
    hist_kernel<<<(B_ * (M_ + N_)) / 256, 256>>>(unknown, known);
    scan_kernel<<<4, 1024>>>();
    scatter_kernel<<<(B_ * (M_ + N_)) / 256, 256>>>(unknown, known);

    // 1-NN standalone with cell-level lower-bound pruning
    nn_kernel<<<512, 256>>>();

    // K2: P_t[b][m][o] = (w1[:, :256] @ kf)^T
    gemm_kernel<C2_, false, false, false, true, H1_>
        <<<dim3(M_ / 128, H1_ / 128, B_), 256>>>(
            w1, 384, 0, kf, M_, nullptr, nullptr, nullptr, nullptr, pP, nullptr);

    // h = w1[:, 256:] @ unknow_feats + gather(P_t, idx); stats1
    gemm_kernel<C1_, true, false, true, false, H1_>
        <<<dim3(N_ / 128, H1_ / 128, B_), 256>>>(
            w1, 384, C2_, uf, N_, pP, pidx, nullptr, nullptr, ph, pp1);

    fin_kernel<H1_><<<H1_, 128>>>(pp1, gamma1, beta1, ps1, pb1, invN);

    // out_pre = w2 @ relu(bn1(h)); stats2
    gemm_kernel<H1_, false, true, true, false, H2_>
        <<<dim3(N_ / 128, H2_ / 128, B_), 256>>>(
            w2, 256, 0, ph, N_, nullptr, nullptr, ps1, pb1, out, pp2);

    fin_kernel<H2_><<<H2_, 128>>>(pp2, gamma2, beta2, ps2, pb2, invN);

    bnfin_kernel<<<dim3(N_ / 1024, B_ * H2_), 256>>>(out, ps2, pb2);
}

// round 16
// speedup vs baseline: 4.1219x; 1.1079x over previous
#include <cuda_runtime.h>
#include <cstdint>

// ---------------------------------------------------------------------------
// Problem constants
// ---------------------------------------------------------------------------
#define B_   2
#define N_   65536
#define M_   16384
#define C1_  128
#define C2_  256
#define H1_  256
#define H2_  128
#define NT_  512
#define EPS_ 1e-5f
#define CELLS 32768          // 32^3 grid per batch, h = 0.25

// ---------------------------------------------------------------------------
// Scratch (device globals -- no allocation allowed)
// ---------------------------------------------------------------------------
__device__ int    g_idx[B_ * N_];
__device__ float  g_P[(size_t)B_ * M_ * H1_];      // TRANSPOSED: [b][m][o]
__device__ float  g_h[(size_t)B_ * H1_ * N_];
__device__ float  g_part1[(size_t)B_ * H1_ * NT_ * 2];
__device__ float  g_part2[(size_t)B_ * H2_ * NT_ * 2];
__device__ float  g_scale1[H1_], g_bias1[H1_];
__device__ float  g_scale2[H2_], g_bias2[H2_];

// pre-converted fragment-order W (tf32) per GEMM:
//   K2: 2 otiles x 8 kt; K3: 2 x 4; K5: 1 x 8   (x 4096 words each)
#define WF_K2 0
#define WF_K3 (WF_K2 + 2 * 8 * 4096)
#define WF_K5 (WF_K3 + 2 * 4 * 4096)
#define WF_TOT (WF_K5 + 1 * 8 * 4096)
__device__ __align__(16) uint32_t g_wf[WF_TOT];

// grid-NN scratch
__device__ int    g_kcnt[B_ * CELLS], g_kstart[B_ * CELLS], g_kcur[B_ * CELLS];
__device__ int    g_qcnt[B_ * CELLS], g_qstart[B_ * CELLS], g_qcur[B_ * CELLS];
__device__ int    g_kcell[B_ * M_],  g_qcell[B_ * N_];
__device__ __align__(16) float4 g_ksort[B_ * M_];
__device__ __align__(16) float4 g_qsort[B_ * N_];
__device__ int    g_korig[B_ * M_], g_qorig[B_ * N_];

// ---------------------------------------------------------------------------
// helpers
// ---------------------------------------------------------------------------
__device__ __forceinline__ uint32_t cvt_tf32(float f) {
    uint32_t u;
    asm("cvt.rna.tf32.f32 %0, %1;" : "=r"(u) : "f"(f));
    return u;
}
__device__ __forceinline__ void mma_tf32(float* c, const uint32_t* a,
                                         uint32_t b0, uint32_t b1) {
    asm volatile(
        "mma.sync.aligned.m16n8k8.row.col.f32.tf32.tf32.f32 "
        "{%0,%1,%2,%3}, {%4,%5,%6,%7}, {%8,%9}, {%0,%1,%2,%3};\n"
        : "+f"(c[0]), "+f"(c[1]), "+f"(c[2]), "+f"(c[3])
        : "r"(a[0]), "r"(a[1]), "r"(a[2]), "r"(a[3]), "r"(b0), "r"(b1));
}
__device__ __forceinline__ int cellof(float v) {
    int c = __float2int_rd((v + 4.0f) * 4.0f);
    return min(31, max(0, c));
}
// per-axis distance from q to cell slab [lo, hi); clamped cells extend to inf
__device__ __forceinline__ float axdist(float qv, int c) {
    float lo = -4.0f + 0.25f * (float)c;
    float hi = lo + 0.25f;
    float d = fmaxf(lo - qv, qv - hi);
    if (c == 0)  d = fminf(d, qv - hi);
    if (c == 31) d = fmaxf(lo - qv, 0.f);
    return fmaxf(d, 0.f);
}

// ---------------------------------------------------------------------------
// prep_w: convert W slice into the exact fragment-order layout the GEMM
// staging used to build per k-tile. Same cvt.rna values, same positions ->
// bitwise-identical MMA inputs.
//   word layout (4096 words per (otile, kt)):
//     addr = ((s*8 + mt)*32 + (o&7)*4 + (c&3))*4 + ((o>>3)&1) + ((c>>2)<<1)
//   with o in [0,128), k in [0,32), s=k>>3, c=k&7, mt=o>>4.
// Inverse used here: from word -> (o, k).
// ---------------------------------------------------------------------------
__global__ void prep_w_kernel(const float* __restrict__ W, int ldw, int woff,
                              int NKT, int OT, int wfbase)
{
    int idx = blockIdx.x * 256 + threadIdx.x;
    int total = OT * NKT * 4096;
    if (idx >= total) return;
    int word = idx & 4095;
    int kt   = (idx >> 12) % NKT;
    int oy   = idx / (NKT * 4096);

    int w2   = word & 3;           // hi + (c>>2)*2
    int lane = (word >> 2) & 31;
    int tile = (word >> 7) & 31;   // s*8 + mt, in [0,32)

    int hi   = w2 & 1;
    int chi  = (w2 >> 1) & 1;
    int g    = lane >> 2;
    int clo  = lane & 3;
    int s    = tile >> 3;
    int mt   = tile & 7;

    int o = mt * 16 + hi * 8 + g;
    int k = s * 8 + chi * 4 + clo;

    float v = W[(size_t)(oy * 128 + o) * ldw + woff + kt * 32 + k];
    g_wf[wfbase + idx] = cvt_tf32(v);
}

// ---------------------------------------------------------------------------
// Binning: zero counters -> histogram -> scan -> scatter  (round-15 exact)
// ---------------------------------------------------------------------------
__global__ void zero_kernel() {
    int i = blockIdx.x * 256 + threadIdx.x;
    if (i < B_ * CELLS) { g_kcnt[i] = 0; g_qcnt[i] = 0; }
}

__global__ void hist_kernel(const float* __restrict__ unknown,
                            const float* __restrict__ known) {
    int j = blockIdx.x * 256 + threadIdx.x;
    if (j < B_ * M_) {
        float x = known[3 * j], y = known[3 * j + 1], z = known[3 * j + 2];
        int cell = (cellof(z) * 32 + cellof(y)) * 32 + cellof(x);
        g_kcell[j] = cell;
        atomicAdd(&g_kcnt[(j / M_) * CELLS + cell], 1);
    } else {
        int q = j - B_ * M_;
        if (q < B_ * N_) {
            float x = unknown[3 * q], y = unknown[3 * q + 1], z = unknown[3 * q + 2];
            int cell = (cellof(z) * 32 + cellof(y)) * 32 + cellof(x);
            g_qcell[q] = cell;
            atomicAdd(&g_qcnt[(q / N_) * CELLS + cell], 1);
        }
    }
}

__global__ void __launch_bounds__(1024) scan_kernel() {
    const int w = blockIdx.x;
    int* cnt;  int* start;  int* cur;
    if (w < 2) { cnt = g_kcnt + w * CELLS; start = g_kstart + w * CELLS; cur = g_kcur + w * CELLS; }
    else { int b = w - 2; cnt = g_qcnt + b * CELLS; start = g_qstart + b * CELLS; cur = g_qcur + b * CELLS; }
    const int t = threadIdx.x;
    int loc[32]; int s = 0;
#pragma unroll
    for (int i = 0; i < 32; i++) { loc[i] = s; s += cnt[t * 32 + i]; }
    const int lane = t & 31, wid = t >> 5;
    int v = s;
#pragma unroll
    for (int off = 1; off < 32; off <<= 1) {
        int n = __shfl_up_sync(0xffffffffu, v, off);
        if (lane >= off) v += n;
    }
    __shared__ int ws[32];
    if (lane == 31) ws[wid] = v;
    __syncthreads();
    if (wid == 0) {
        int x = ws[lane];
#pragma unroll
        for (int off = 1; off < 32; off <<= 1) {
            int n = __shfl_up_sync(0xffffffffu, x, off);
            if (lane >= off) x += n;
        }
        ws[lane] = x;
    }
    __syncthreads();
    int base = v - s + (wid > 0 ? ws[wid - 1] : 0);
#pragma unroll
    for (int i = 0; i < 32; i++) {
        int val = base + loc[i];
        start[t * 32 + i] = val;
        cur[t * 32 + i] = val;
    }
}

__global__ void scatter_kernel(const float* __restrict__ unknown,
                               const float* __restrict__ known) {
    int j = blockIdx.x * 256 + threadIdx.x;
    if (j < B_ * M_) {
        int b = j / M_;
        float x = known[3 * j], y = known[3 * j + 1], z = known[3 * j + 2];
        float k2 = __fadd_rn(__fadd_rn(__fmul_rn(x, x), __fmul_rn(y, y)),
                             __fmul_rn(z, z));
        int pos = atomicAdd(&g_kcur[b * CELLS + g_kcell[j]], 1);
        g_ksort[b * M_ + pos] = make_float4(x, y, z, k2);
        g_korig[b * M_ + pos] = j - b * M_;
    } else {
        int q = j - B_ * M_;
        if (q < B_ * N_) {
            int b = q / N_;
            float x = unknown[3 * q], y = unknown[3 * q + 1], z = unknown[3 * q + 2];
            float u2 = __fadd_rn(__fadd_rn(__fmul_rn(x, x), __fmul_rn(y, y)),
                                 __fmul_rn(z, z));
            int pos = atomicAdd(&g_qcur[b * CELLS + g_qcell[q]], 1);
            g_qsort[(size_t)b * N_ + pos] = make_float4(x, y, z, u2);
            g_qorig[(size_t)b * N_ + pos] = q - b * N_;
        }
    }
}

// ---------------------------------------------------------------------------
// Grid-pruned exact 1-NN with cell lower-bound pruning (round-15 VERBATIM).
// ---------------------------------------------------------------------------
__global__ void __launch_bounds__(256) nn_kernel() {
    const int gq = blockIdx.x * 256 + threadIdx.x;
    const int b = gq / N_;
    const float4 q = g_qsort[gq];
    const int oq = g_qorig[gq];
    const int qx = cellof(q.x), qy = cellof(q.y), qz = cellof(q.z);
    float bd = 3.4e38f; int bi = 0;
    const float4* kp = g_ksort + (size_t)b * M_;
    const int*    ko = g_korig + (size_t)b * M_;
    const int*    st = g_kstart + b * CELLS;
    const int*    ct = g_kcnt + b * CELLS;

    for (int r = 0; r <= 31; r++) {
        if (r > 0) {
            float rr = (float)(r - 1) * 0.25f;
            if (bd + 4e-3f <= rr * rr) break;
        }
        int zlo = max(qz - r, 0), zhi = min(qz + r, 31);
        for (int cz = zlo; cz <= zhi; cz++) {
            float dz = axdist(q.z, cz);
            float dz2 = dz * dz;
            if (bd + 4e-3f <= dz2) continue;
            int adz = (cz > qz) ? (cz - qz) : (qz - cz);
            int ylo = max(qy - r, 0), yhi = min(qy + r, 31);
            for (int cy = ylo; cy <= yhi; cy++) {
                float dy = axdist(q.y, cy);
                float dyz2 = fmaf(dy, dy, dz2);
                if (bd + 4e-3f <= dyz2) continue;
                int ady = (cy > qy) ? (cy - qy) : (qy - cy);
                int xlo, xhi, xstep;
                if (adz == r || ady == r) {
                    xlo = max(qx - r, 0); xhi = min(qx + r, 31); xstep = 1;
                } else {
                    xlo = qx - r; xhi = qx + r; xstep = 2 * r;
                }
                for (int cx = xlo; cx <= xhi; cx += xstep) {
                    if ((unsigned)cx > 31u) continue;
                    float dx = axdist(q.x, cx);
                    float mind2 = fmaf(dx, dx, dyz2);
                    if (bd + 4e-3f <= mind2) continue;
                    int cell = (cz * 32 + cy) * 32 + cx;
                    int s = st[cell], e = s + ct[cell];
                    for (int jj = s; jj < e; jj++) {
                        float4 k4 = kp[jj];
                        float dot = __fmul_rn(q.x, k4.x);
                        dot = fmaf(q.y, k4.y, dot);
                        dot = fmaf(q.z, k4.z, dot);
                        float d = __fadd_rn(fmaf(-2.0f, dot, q.w), k4.w);
                        int o = ko[jj];
                        if (d < bd) { bd = d; bi = o; }
                        else if (d == bd && o < bi) { bi = o; }
                    }
                }
            }
        }
    }
    g_idx[(size_t)b * N_ + oq] = bi;
}

// ---------------------------------------------------------------------------
// Tensor-core (tf32 mma.sync) GEMM; W staged by pure coalesced copy from the
// pre-converted fragment-order g_wf (bitwise-identical MMA inputs).
// ---------------------------------------------------------------------------
template <int KDIM, bool GATHER, bool BN, bool STATS, bool TRANSOUT, int MTOT>
__global__ void __launch_bounds__(256, 2) gemm_kernel(
    int wfbase,
    const float* __restrict__ X, int N,
    const float* __restrict__ P,
    const int*   __restrict__ idx,
    const float* __restrict__ bsc,
    const float* __restrict__ bbi,
    float* __restrict__ Y,
    float* __restrict__ part)
{
    __shared__ __align__(16) uint32_t SH[16384];
    __shared__ int idbuf[128];

    const int b   = blockIdx.z;
    const int ob0 = blockIdx.y * 128;
    const int ib0 = blockIdx.x * 128;
    const int nbx = gridDim.x;
    const int bx  = blockIdx.x;
    const int t   = threadIdx.x;
    const int lane = t & 31, wid = t >> 5;
    const int wo = wid >> 1, wn = wid & 1;
    const int gid = lane >> 2, tig = lane & 3;

    constexpr int NKT = KDIM / 32;
    const float* Xb = X + (size_t)b * KDIM * N;
    const uint32_t* Wf = g_wf + wfbase + (size_t)blockIdx.y * NKT * 4096;

    float acc[2][8][4];
#pragma unroll
    for (int m = 0; m < 2; m++)
#pragma unroll
        for (int n = 0; n < 8; n++)
#pragma unroll
            for (int e = 0; e < 4; e++) acc[m][n][e] = 0.f;

    const int x_k   = t >> 3;
    const int x_i0  = (t & 7) * 16;
    const int x_s   = x_k >> 3;
    const int x_tig = x_k & 3, x_hi = (x_k >> 2) & 1;

    int buf = 0;
    for (int kt = 0; kt < NKT; ++kt) {
        const int k0 = kt * 32;
        uint32_t* Ab = SH + buf * 4096;
        uint32_t* Bb = SH + 8192 + buf * 4096;

        // ---- W tile: pure coalesced copy from fragment-order gmem ----
        {
            const uint32_t* src = Wf + kt * 4096;
#pragma unroll
            for (int j = 0; j < 4; j++) {
                int w = j * 1024 + t * 4;
                *(uint4*)&Ab[w] = *(const uint4*)&src[w];
            }
        }
        // ---- X tile staging (+BN) unchanged ----
        {
            const float* xr = Xb + (size_t)(k0 + x_k) * N + ib0 + x_i0;
            float bs = 0.f, bb = 0.f;
            if (BN) { bs = bsc[k0 + x_k]; bb = bbi[k0 + x_k]; }
#pragma unroll
            for (int j = 0; j < 4; j++) {
                float4 v = *(const float4*)(xr + j * 4);
                if (BN) {
                    v.x = fmaxf(fmaf(v.x, bs, bb), 0.f);
                    v.y = fmaxf(fmaf(v.y, bs, bb), 0.f);
                    v.z = fmaxf(fmaf(v.z, bs, bb), 0.f);
                    v.w = fmaxf(fmaf(v.w, bs, bb), 0.f);
                }
                uint32_t q[4] = {cvt_tf32(v.x), cvt_tf32(v.y), cvt_tf32(v.z), cvt_tf32(v.w)};
#pragma unroll
                for (int e = 0; e < 4; e++) {
                    int i = x_i0 + j * 4 + e;
                    int nt = i >> 3, gg = i & 7;
                    Bb[(((x_s * 8 + (nt >> 1)) * 32 + gg * 4 + x_tig) << 2)
                       + (nt & 1) * 2 + x_hi] = q[e];
                }
            }
        }
        __syncthreads();
#pragma unroll
        for (int s = 0; s < 4; s++) {
            uint4 af[2];
            af[0] = *(const uint4*)&Ab[((s * 8 + wo * 2 + 0) * 32 + lane) << 2];
            af[1] = *(const uint4*)&Ab[((s * 8 + wo * 2 + 1) * 32 + lane) << 2];
            uint4 bf[4];
#pragma unroll
            for (int p = 0; p < 4; p++)
                bf[p] = *(const uint4*)&Bb[((s * 8 + wn * 4 + p) * 32 + lane) << 2];
#pragma unroll
            for (int m = 0; m < 2; m++)
#pragma unroll
                for (int p = 0; p < 4; p++) {
                    mma_tf32(acc[m][2 * p],     (const uint32_t*)&af[m], bf[p].x, bf[p].y);
                    mma_tf32(acc[m][2 * p + 1], (const uint32_t*)&af[m], bf[p].z, bf[p].w);
                }
        }
        buf ^= 1;
    }

    const int o_base = ob0 + wo * 32;
    const int i_base = ib0 + wn * 64;

    if (GATHER) {
        __syncthreads();
        if (t < 128) idbuf[t] = idx[(size_t)b * N + ib0 + t];
        __syncthreads();
        float* G = (float*)SH;
#pragma unroll
        for (int j = 0; j < 16; j++) {
            int lin = t + j * 256;
            int r = lin >> 5, c4 = (lin & 31) << 2;
            const float* src = P + ((size_t)b * M_ + idbuf[r]) * MTOT + ob0 + c4;
            *(float4*)&G[r * 128 + c4] = *(const float4*)src;
        }
        __syncthreads();
        const int i0l = wn * 64 + tig * 2;
        const int o0l = wo * 32 + gid;
#pragma unroll
        for (int m = 0; m < 2; m++) {
            int oo = o0l + m * 16;
#pragma unroll
            for (int n = 0; n < 8; n++) {
                int ii = i0l + n * 8;
                acc[m][n][0] += G[ii * 128 + oo];
                acc[m][n][1] += G[(ii + 1) * 128 + oo];
                acc[m][n][2] += G[ii * 128 + oo + 8];
                acc[m][n][3] += G[(ii + 1) * 128 + oo + 8];
            }
        }
    }

    if (TRANSOUT) {
#pragma unroll
        for (int m = 0; m < 2; m++)
#pragma unroll
            for (int n = 0; n < 8; n++) {
                int i_ = i_base + n * 8 + tig * 2;
                int o_ = o_base + m * 16 + gid;
                float* Yr = Y + ((size_t)b * N + i_) * MTOT;
                Yr[o_]            = acc[m][n][0];
                Yr[MTOT + o_]     = acc[m][n][1];
                Yr[o_ + 8]        = acc[m][n][2];
                Yr[MTOT + o_ + 8] = acc[m][n][3];
            }
    } else {
#pragma unroll
        for (int m = 0; m < 2; m++) {
            float* Y0 = Y + ((size_t)b * MTOT + o_base + m * 16 + gid) * N + i_base + tig * 2;
            float* Y8 = Y0 + (size_t)8 * N;
#pragma unroll
            for (int n = 0; n < 8; n++) {
                *(float2*)(Y0 + n * 8) = make_float2(acc[m][n][0], acc[m][n][1]);
                *(float2*)(Y8 + n * 8) = make_float2(acc[m][n][2], acc[m][n][3]);
            }
        }
    }

    if (STATS) {
        float s1[2][2], s2[2][2];
#pragma unroll
        for (int m = 0; m < 2; m++) {
            float a0 = 0.f, q0 = 0.f, a1 = 0.f, q1 = 0.f;
#pragma unroll
            for (int n = 0; n < 8; n++) {
                a0 += acc[m][n][0]; q0 = fmaf(acc[m][n][0], acc[m][n][0], q0);
                a0 += acc[m][n][1]; q0 = fmaf(acc[m][n][1], acc[m][n][1], q0);
                a1 += acc[m][n][2]; q1 = fmaf(acc[m][n][2], acc[m][n][2], q1);
                a1 += acc[m][n][3]; q1 = fmaf(acc[m][n][3], acc[m][n][3], q1);
            }
            s1[m][0] = a0; s2[m][0] = q0; s1[m][1] = a1; s2[m][1] = q1;
        }
#pragma unroll
        for (int m = 0; m < 2; m++)
#pragma unroll
            for (int h = 0; h < 2; h++) {
#pragma unroll
                for (int off = 1; off <= 2; off <<= 1) {
                    s1[m][h] += __shfl_xor_sync(0xffffffffu, s1[m][h], off);
                    s2[m][h] += __shfl_xor_sync(0xffffffffu, s2[m][h], off);
                }
            }
        float* sb1 = (float*)SH;
        float* sb2 = sb1 + 256;
        __syncthreads();
        if (tig == 0) {
#pragma unroll
            for (int m = 0; m < 2; m++)
#pragma unroll
                for (int h = 0; h < 2; h++) {
                    int ol = wo * 32 + m * 16 + h * 8 + gid;
                    sb1[wn * 128 + ol] = s1[m][h];
                    sb2[wn * 128 + ol] = s2[m][h];
                }
        }
        __syncthreads();
        if (t < 128) {
            float tot = sb1[t] + sb1[128 + t];
            part[(((size_t)b * MTOT + ob0 + t) * nbx + bx) * 2 + 0] = tot;
        } else {
            int o = t - 128;
            float tot = sb2[o] + sb2[128 + o];
            part[(((size_t)b * MTOT + ob0 + o) * nbx + bx) * 2 + 1] = tot;
        }
    }
}

// ---------------------------------------------------------------------------
// Finalize BN stats: one block per channel
// ---------------------------------------------------------------------------
template <int MTOT>
__global__ void __launch_bounds__(128) fin_kernel(
    const float* __restrict__ part,
    const float* __restrict__ gamma, const float* __restrict__ beta,
    float* __restrict__ sc, float* __restrict__ bi, float invN)
{
    const int o = blockIdx.x;
    const int t = threadIdx.x;
    float s1 = 0.f, s2 = 0.f;
    for (int b = 0; b < B_; b++) {
        const float* p = part + ((size_t)b * MTOT + o) * NT_ * 2;
        for (int q = t; q < NT_; q += 128) {
            s1 += p[q * 2 + 0];
            s2 += p[q * 2 + 1];
        }
    }
#pragma unroll
    for (int off = 16; off; off >>= 1) {
        s1 += __shfl_down_sync(0xffffffffu, s1, off);
        s2 += __shfl_down_sync(0xffffffffu, s2, off);
    }
    __shared__ float r1[4], r2[4];
    if ((t & 31) == 0) { r1[t >> 5] = s1; r2[t >> 5] = s2; }
    __syncthreads();
    if (t == 0) {
        s1 = r1[0] + r1[1] + r1[2] + r1[3];
        s2 = r2[0] + r2[1] + r2[2] + r2[3];
        float mean = s1 * invN;
        float var  = s2 * invN - mean * mean;
        float rstd = rsqrtf(var + EPS_);
        float s    = gamma[o] * rstd;
        sc[o] = s;
        bi[o] = beta[o] - mean * s;
    }
}

// ---------------------------------------------------------------------------
// Final elementwise BN+ReLU in-place on d_out
// ---------------------------------------------------------------------------
__global__ void __launch_bounds__(256) bnfin_kernel(
    float* __restrict__ Y, const float* __restrict__ sc, const float* __restrict__ bi)
{
    int row = blockIdx.y;
    int ch  = row & (H2_ - 1);
    size_t base = (size_t)row * N_;
    int i = (blockIdx.x * 256 + threadIdx.x) * 4;
    float4 v = *(float4*)(Y + base + i);
    float s = sc[ch], b = bi[ch];
    v.x = fmaxf(fmaf(v.x, s, b), 0.f);
    v.y = fmaxf(fmaf(v.y, s, b), 0.f);
    v.z = fmaxf(fmaf(v.z, s, b), 0.f);
    v.w = fmaxf(fmaf(v.w, s, b), 0.f);
    *(float4*)(Y + base + i) = v;
}

// ---------------------------------------------------------------------------
// Launch
// ---------------------------------------------------------------------------
extern "C" void kernel_launch(void* const* d_in, const int* in_sizes, int n_in,
                              void* d_out, int out_size)
{
    const float* unknown = (const float*)d_in[0];
    const float* known   = (const float*)d_in[1];
    const float* uf      = (const float*)d_in[2];
    const float* kf      = (const float*)d_in[3];
    const float* w1      = (const float*)d_in[4];
    const float* gamma1  = (const float*)d_in[5];
    const float* beta1   = (const float*)d_in[6];
    const float* w2      = (const float*)d_in[7];
    const float* gamma2  = (const float*)d_in[8];
    const float* beta2   = (const float*)d_in[9];
    float* out = (float*)d_out;

    float *pP, *ph, *pp1, *pp2, *ps1, *pb1, *ps2, *pb2;
    int* pidx;
    cudaGetSymbolAddress((void**)&pP,   g_P);
    cudaGetSymbolAddress((void**)&ph,   g_h);
    cudaGetSymbolAddress((void**)&pp1,  g_part1);
    cudaGetSymbolAddress((void**)&pp2,  g_part2);
    cudaGetSymbolAddress((void**)&ps1,  g_scale1);
    cudaGetSymbolAddress((void**)&pb1,  g_bias1);
    cudaGetSymbolAddress((void**)&ps2,  g_scale2);
    cudaGetSymbolAddress((void**)&pb2,  g_bias2);
    cudaGetSymbolAddress((void**)&pidx, g_idx);

    const float invN = 1.0f / (float)(B_ * N_);

    // W fragment pre-conversion (K2: w1[:, :256]; K3: w1[:, 256:]; K5: w2)
    prep_w_kernel<<<(2 * 8 * 4096) / 256, 256>>>(w1, 384, 0,   8, 2, WF_K2);
    prep_w_kernel<<<(2 * 4 * 4096) / 256, 256>>>(w1, 384, 256, 4, 2, WF_K3);
    prep_w_kernel<<<(1 * 8 * 4096) / 256, 256>>>(w2, 256, 0,   8, 1, WF_K5);

    // grid binning for pruned 1-NN (32^3)
    zero_kernel<<<256, 256>>>();
    hist_kernel<<<(B_ * (M_ + N_)) / 256, 256>>>(unknown, known);
    scan_kernel<<<4, 1024>>>();
    scatter_kernel<<<(B_ * (M_ + N_)) / 256, 256>>>(unknown, known);

    // 1-NN standalone with cell-level lower-bound pruning
    nn_kernel<<<512, 256>>>();

    // K2: P_t[b][m][o] = (w1[:, :256] @ kf)^T
    gemm_kernel<C2_, false, false, false, true, H1_>
        <<<dim3(M_ / 128, H1_ / 128, B_), 256>>>(
            WF_K2, kf, M_, nullptr, nullptr, nullptr, nullptr, pP, nullptr);

    // K3: h = w1[:, 256:] @ uf + gather(P_t, idx); stats1
    gemm_kernel<C1_, true, false, true, false, H1_>
        <<<dim3(N_ / 128, H1_ / 128, B_), 256>>>(
            WF_K3, uf, N_, pP, pidx, nullptr, nullptr, ph, pp1);

    fin_kernel<H1_><<<H1_, 128>>>(pp1, gamma1, beta1, ps1, pb1, invN);

    // K5: out_pre = w2 @ relu(bn1(h)); stats2
    gemm_kernel<H1_, false, true, true, false, H2_>
        <<<dim3(N_ / 128, H2_ / 128, B_), 256>>>(
            WF_K5, ph, N_, nullptr, nullptr, ps1, pb1, out, pp2);

    fin_kernel<H2_><<<H2_, 128>>>(pp2, gamma2, beta2, ps2, pb2, invN);

    bnfin_kernel<<<dim3(N_ / 1024, B_ * H2_), 256>>>(out, ps2, pb2);
}

// round 17
// speedup vs baseline: 4.2975x; 1.0426x over previous
#include <cuda_runtime.h>
#include <cstdint>

// ---------------------------------------------------------------------------
// Problem constants
// ---------------------------------------------------------------------------
#define B_   2
#define N_   65536
#define M_   16384
#define C1_  128
#define C2_  256
#define H1_  256
#define H2_  128
#define NT_  512
#define EPS_ 1e-5f
#define CELLS 32768          // 32^3 grid per batch, h = 0.25

// ---------------------------------------------------------------------------
// Scratch (device globals -- no allocation allowed)
// ---------------------------------------------------------------------------
__device__ int    g_idx[B_ * N_];
__device__ float  g_P[(size_t)B_ * M_ * H1_];      // TRANSPOSED: [b][m][o]
__device__ float  g_h[(size_t)B_ * H1_ * N_];
__device__ float  g_part1[(size_t)B_ * H1_ * NT_ * 2];
__device__ float  g_part2[(size_t)B_ * H2_ * NT_ * 2];
__device__ float  g_scale1[H1_], g_bias1[H1_];
__device__ float  g_scale2[H2_], g_bias2[H2_];

// pre-converted fragment-order W (tf32) per GEMM
#define WF_K2 0
#define WF_K3 (WF_K2 + 2 * 8 * 4096)
#define WF_K5 (WF_K3 + 2 * 4 * 4096)
#define WF_TOT (WF_K5 + 1 * 8 * 4096)
__device__ __align__(16) uint32_t g_wf[WF_TOT];

// grid-NN scratch
__device__ int    g_kcnt[B_ * CELLS], g_kstart[B_ * CELLS], g_kcur[B_ * CELLS];
__device__ int    g_qcnt[B_ * CELLS], g_qstart[B_ * CELLS], g_qcur[B_ * CELLS];
__device__ int    g_kcell[B_ * M_],  g_qcell[B_ * N_];
__device__ __align__(16) float4 g_ksort[B_ * M_];
__device__ __align__(16) float4 g_qsort[B_ * N_];
__device__ int    g_korig[B_ * M_], g_qorig[B_ * N_];

// ---------------------------------------------------------------------------
// helpers
// ---------------------------------------------------------------------------
__device__ __forceinline__ uint32_t cvt_tf32(float f) {
    uint32_t u;
    asm("cvt.rna.tf32.f32 %0, %1;" : "=r"(u) : "f"(f));
    return u;
}
__device__ __forceinline__ void mma_tf32(float* c, const uint32_t* a,
                                         uint32_t b0, uint32_t b1) {
    asm volatile(
        "mma.sync.aligned.m16n8k8.row.col.f32.tf32.tf32.f32 "
        "{%0,%1,%2,%3}, {%4,%5,%6,%7}, {%8,%9}, {%0,%1,%2,%3};\n"
        : "+f"(c[0]), "+f"(c[1]), "+f"(c[2]), "+f"(c[3])
        : "r"(a[0]), "r"(a[1]), "r"(a[2]), "r"(a[3]), "r"(b0), "r"(b1));
}
__device__ __forceinline__ int cellof(float v) {
    int c = __float2int_rd((v + 4.0f) * 4.0f);
    return min(31, max(0, c));
}
__device__ __forceinline__ float axdist(float qv, int c) {
    float lo = -4.0f + 0.25f * (float)c;
    float hi = lo + 0.25f;
    float d = fmaxf(lo - qv, qv - hi);
    if (c == 0)  d = fminf(d, qv - hi);
    if (c == 31) d = fmaxf(lo - qv, 0.f);
    return fmaxf(d, 0.f);
}

// ---------------------------------------------------------------------------
// prep_w (round-16 exact): W slice -> fragment-order tf32 in gmem
// ---------------------------------------------------------------------------
__global__ void prep_w_kernel(const float* __restrict__ W, int ldw, int woff,
                              int NKT, int OT, int wfbase)
{
    int idx = blockIdx.x * 256 + threadIdx.x;
    int total = OT * NKT * 4096;
    if (idx >= total) return;
    int word = idx & 4095;
    int kt   = (idx >> 12) % NKT;
    int oy   = idx / (NKT * 4096);

    int w2   = word & 3;
    int lane = (word >> 2) & 31;
    int tile = (word >> 7) & 31;

    int hi   = w2 & 1;
    int chi  = (w2 >> 1) & 1;
    int g    = lane >> 2;
    int clo  = lane & 3;
    int s    = tile >> 3;
    int mt   = tile & 7;

    int o = mt * 16 + hi * 8 + g;
    int k = s * 8 + chi * 4 + clo;

    float v = W[(size_t)(oy * 128 + o) * ldw + woff + kt * 32 + k];
    g_wf[wfbase + idx] = cvt_tf32(v);
}

// ---------------------------------------------------------------------------
// Binning (round-15/16 exact)
// ---------------------------------------------------------------------------
__global__ void zero_kernel() {
    int i = blockIdx.x * 256 + threadIdx.x;
    if (i < B_ * CELLS) { g_kcnt[i] = 0; g_qcnt[i] = 0; }
}

__global__ void hist_kernel(const float* __restrict__ unknown,
                            const float* __restrict__ known) {
    int j = blockIdx.x * 256 + threadIdx.x;
    if (j < B_ * M_) {
        float x = known[3 * j], y = known[3 * j + 1], z = known[3 * j + 2];
        int cell = (cellof(z) * 32 + cellof(y)) * 32 + cellof(x);
        g_kcell[j] = cell;
        atomicAdd(&g_kcnt[(j / M_) * CELLS + cell], 1);
    } else {
        int q = j - B_ * M_;
        if (q < B_ * N_) {
            float x = unknown[3 * q], y = unknown[3 * q + 1], z = unknown[3 * q + 2];
            int cell = (cellof(z) * 32 + cellof(y)) * 32 + cellof(x);
            g_qcell[q] = cell;
            atomicAdd(&g_qcnt[(q / N_) * CELLS + cell], 1);
        }
    }
}

__global__ void __launch_bounds__(1024) scan_kernel() {
    const int w = blockIdx.x;
    int* cnt;  int* start;  int* cur;
    if (w < 2) { cnt = g_kcnt + w * CELLS; start = g_kstart + w * CELLS; cur = g_kcur + w * CELLS; }
    else { int b = w - 2; cnt = g_qcnt + b * CELLS; start = g_qstart + b * CELLS; cur = g_qcur + b * CELLS; }
    const int t = threadIdx.x;
    int loc[32]; int s = 0;
#pragma unroll
    for (int i = 0; i < 32; i++) { loc[i] = s; s += cnt[t * 32 + i]; }
    const int lane = t & 31, wid = t >> 5;
    int v = s;
#pragma unroll
    for (int off = 1; off < 32; off <<= 1) {
        int n = __shfl_up_sync(0xffffffffu, v, off);
        if (lane >= off) v += n;
    }
    __shared__ int ws[32];
    if (lane == 31) ws[wid] = v;
    __syncthreads();
    if (wid == 0) {
        int x = ws[lane];
#pragma unroll
        for (int off = 1; off < 32; off <<= 1) {
            int n = __shfl_up_sync(0xffffffffu, x, off);
            if (lane >= off) x += n;
        }
        ws[lane] = x;
    }
    __syncthreads();
    int base = v - s + (wid > 0 ? ws[wid - 1] : 0);
#pragma unroll
    for (int i = 0; i < 32; i++) {
        int val = base + loc[i];
        start[t * 32 + i] = val;
        cur[t * 32 + i] = val;
    }
}

__global__ void scatter_kernel(const float* __restrict__ unknown,
                               const float* __restrict__ known) {
    int j = blockIdx.x * 256 + threadIdx.x;
    if (j < B_ * M_) {
        int b = j / M_;
        float x = known[3 * j], y = known[3 * j + 1], z = known[3 * j + 2];
        float k2 = __fadd_rn(__fadd_rn(__fmul_rn(x, x), __fmul_rn(y, y)),
                             __fmul_rn(z, z));
        int pos = atomicAdd(&g_kcur[b * CELLS + g_kcell[j]], 1);
        g_ksort[b * M_ + pos] = make_float4(x, y, z, k2);
        g_korig[b * M_ + pos] = j - b * M_;
    } else {
        int q = j - B_ * M_;
        if (q < B_ * N_) {
            int b = q / N_;
            float x = unknown[3 * q], y = unknown[3 * q + 1], z = unknown[3 * q + 2];
            float u2 = __fadd_rn(__fadd_rn(__fmul_rn(x, x), __fmul_rn(y, y)),
                                 __fmul_rn(z, z));
            int pos = atomicAdd(&g_qcur[b * CELLS + g_qcell[q]], 1);
            g_qsort[(size_t)b * N_ + pos] = make_float4(x, y, z, u2);
            g_qorig[(size_t)b * N_ + pos] = q - b * N_;
        }
    }
}

// ---------------------------------------------------------------------------
// NN body (round-15 VERBATIM): grid-pruned exact 1-NN with cell bounds.
// ---------------------------------------------------------------------------
__device__ __forceinline__ void nn_body(int gq) {
    const int b = gq / N_;
    const float4 q = g_qsort[gq];
    const int oq = g_qorig[gq];
    const int qx = cellof(q.x), qy = cellof(q.y), qz = cellof(q.z);
    float bd = 3.4e38f; int bi = 0;
    const float4* kp = g_ksort + (size_t)b * M_;
    const int*    ko = g_korig + (size_t)b * M_;
    const int*    st = g_kstart + b * CELLS;
    const int*    ct = g_kcnt + b * CELLS;

    for (int r = 0; r <= 31; r++) {
        if (r > 0) {
            float rr = (float)(r - 1) * 0.25f;
            if (bd + 4e-3f <= rr * rr) break;
        }
        int zlo = max(qz - r, 0), zhi = min(qz + r, 31);
        for (int cz = zlo; cz <= zhi; cz++) {
            float dz = axdist(q.z, cz);
            float dz2 = dz * dz;
            if (bd + 4e-3f <= dz2) continue;
            int adz = (cz > qz) ? (cz - qz) : (qz - cz);
            int ylo = max(qy - r, 0), yhi = min(qy + r, 31);
            for (int cy = ylo; cy <= yhi; cy++) {
                float dy = axdist(q.y, cy);
                float dyz2 = fmaf(dy, dy, dz2);
                if (bd + 4e-3f <= dyz2) continue;
                int ady = (cy > qy) ? (cy - qy) : (qy - cy);
                int xlo, xhi, xstep;
                if (adz == r || ady == r) {
                    xlo = max(qx - r, 0); xhi = min(qx + r, 31); xstep = 1;
                } else {
                    xlo = qx - r; xhi = qx + r; xstep = 2 * r;
                }
                for (int cx = xlo; cx <= xhi; cx += xstep) {
                    if ((unsigned)cx > 31u) continue;
                    float dx = axdist(q.x, cx);
                    float mind2 = fmaf(dx, dx, dyz2);
                    if (bd + 4e-3f <= mind2) continue;
                    int cell = (cz * 32 + cy) * 32 + cx;
                    int s = st[cell], e = s + ct[cell];
                    for (int jj = s; jj < e; jj++) {
                        float4 k4 = kp[jj];
                        float dot = __fmul_rn(q.x, k4.x);
                        dot = fmaf(q.y, k4.y, dot);
                        dot = fmaf(q.z, k4.z, dot);
                        float d = __fadd_rn(fmaf(-2.0f, dot, q.w), k4.w);
                        int o = ko[jj];
                        if (d < bd) { bd = d; bi = o; }
                        else if (d == bd && o < bi) { bi = o; }
                    }
                }
            }
        }
    }
    g_idx[(size_t)b * N_ + oq] = bi;
}

// ---------------------------------------------------------------------------
// GEMM body (round-16 exact): W staged via coalesced copy from g_wf.
// ---------------------------------------------------------------------------
template <int KDIM, bool GATHER, bool BN, bool STATS, bool TRANSOUT, int MTOT>
__device__ __forceinline__ void gemm_body(
    uint32_t* SH, int* idbuf,
    int b, int ob0, int ib0, int oy, int nbx, int bx,
    int wfbase,
    const float* __restrict__ X, int N,
    const float* __restrict__ P,
    const int*   __restrict__ idx,
    const float* __restrict__ bsc,
    const float* __restrict__ bbi,
    float* __restrict__ Y,
    float* __restrict__ part)
{
    const int t   = threadIdx.x;
    const int lane = t & 31, wid = t >> 5;
    const int wo = wid >> 1, wn = wid & 1;
    const int gid = lane >> 2, tig = lane & 3;

    constexpr int NKT = KDIM / 32;
    const float* Xb = X + (size_t)b * KDIM * N;
    const uint32_t* Wf = g_wf + wfbase + (size_t)oy * NKT * 4096;

    float acc[2][8][4];
#pragma unroll
    for (int m = 0; m < 2; m++)
#pragma unroll
        for (int n = 0; n < 8; n++)
#pragma unroll
            for (int e = 0; e < 4; e++) acc[m][n][e] = 0.f;

    const int x_k   = t >> 3;
    const int x_i0  = (t & 7) * 16;
    const int x_s   = x_k >> 3;
    const int x_tig = x_k & 3, x_hi = (x_k >> 2) & 1;

    int buf = 0;
    for (int kt = 0; kt < NKT; ++kt) {
        const int k0 = kt * 32;
        uint32_t* Ab = SH + buf * 4096;
        uint32_t* Bb = SH + 8192 + buf * 4096;

        {
            const uint32_t* src = Wf + kt * 4096;
#pragma unroll
            for (int j = 0; j < 4; j++) {
                int w = j * 1024 + t * 4;
                *(uint4*)&Ab[w] = *(const uint4*)&src[w];
            }
        }
        {
            const float* xr = Xb + (size_t)(k0 + x_k) * N + ib0 + x_i0;
            float bs = 0.f, bb = 0.f;
            if (BN) { bs = bsc[k0 + x_k]; bb = bbi[k0 + x_k]; }
#pragma unroll
            for (int j = 0; j < 4; j++) {
                float4 v = *(const float4*)(xr + j * 4);
                if (BN) {
                    v.x = fmaxf(fmaf(v.x, bs, bb), 0.f);
                    v.y = fmaxf(fmaf(v.y, bs, bb), 0.f);
                    v.z = fmaxf(fmaf(v.z, bs, bb), 0.f);
                    v.w = fmaxf(fmaf(v.w, bs, bb), 0.f);
                }
                uint32_t qv[4] = {cvt_tf32(v.x), cvt_tf32(v.y), cvt_tf32(v.z), cvt_tf32(v.w)};
#pragma unroll
                for (int e = 0; e < 4; e++) {
                    int i = x_i0 + j * 4 + e;
                    int nt = i >> 3, gg = i & 7;
                    Bb[(((x_s * 8 + (nt >> 1)) * 32 + gg * 4 + x_tig) << 2)
                       + (nt & 1) * 2 + x_hi] = qv[e];
                }
            }
        }
        __syncthreads();
#pragma unroll
        for (int s = 0; s < 4; s++) {
            uint4 af[2];
            af[0] = *(const uint4*)&Ab[((s * 8 + wo * 2 + 0) * 32 + lane) << 2];
            af[1] = *(const uint4*)&Ab[((s * 8 + wo * 2 + 1) * 32 + lane) << 2];
            uint4 bf[4];
#pragma unroll
            for (int p = 0; p < 4; p++)
                bf[p] = *(const uint4*)&Bb[((s * 8 + wn * 4 + p) * 32 + lane) << 2];
#pragma unroll
            for (int m = 0; m < 2; m++)
#pragma unroll
                for (int p = 0; p < 4; p++) {
                    mma_tf32(acc[m][2 * p],     (const uint32_t*)&af[m], bf[p].x, bf[p].y);
                    mma_tf32(acc[m][2 * p + 1], (const uint32_t*)&af[m], bf[p].z, bf[p].w);
                }
        }
        buf ^= 1;
    }

    const int o_base = ob0 + wo * 32;
    const int i_base = ib0 + wn * 64;

    if (GATHER) {
        __syncthreads();
        if (t < 128) idbuf[t] = idx[(size_t)b * N + ib0 + t];
        __syncthreads();
        float* G = (float*)SH;
#pragma unroll
        for (int j = 0; j < 16; j++) {
            int lin = t + j * 256;
            int r = lin >> 5, c4 = (lin & 31) << 2;
            const float* src = P + ((size_t)b * M_ + idbuf[r]) * MTOT + ob0 + c4;
            *(float4*)&G[r * 128 + c4] = *(const float4*)src;
        }
        __syncthreads();
        const int i0l = wn * 64 + tig * 2;
        const int o0l = wo * 32 + gid;
#pragma unroll
        for (int m = 0; m < 2; m++) {
            int oo = o0l + m * 16;
#pragma unroll
            for (int n = 0; n < 8; n++) {
                int ii = i0l + n * 8;
                acc[m][n][0] += G[ii * 128 + oo];
                acc[m][n][1] += G[(ii + 1) * 128 + oo];
                acc[m][n][2] += G[ii * 128 + oo + 8];
                acc[m][n][3] += G[(ii + 1) * 128 + oo + 8];
            }
        }
    }

    if (TRANSOUT) {
#pragma unroll
        for (int m = 0; m < 2; m++)
#pragma unroll
            for (int n = 0; n < 8; n++) {
                int i_ = i_base + n * 8 + tig * 2;
                int o_ = o_base + m * 16 + gid;
                float* Yr = Y + ((size_t)b * N + i_) * MTOT;
                Yr[o_]            = acc[m][n][0];
                Yr[MTOT + o_]     = acc[m][n][1];
                Yr[o_ + 8]        = acc[m][n][2];
                Yr[MTOT + o_ + 8] = acc[m][n][3];
            }
    } else {
#pragma unroll
        for (int m = 0; m < 2; m++) {
            float* Y0 = Y + ((size_t)b * MTOT + o_base + m * 16 + gid) * N + i_base + tig * 2;
            float* Y8 = Y0 + (size_t)8 * N;
#pragma unroll
            for (int n = 0; n < 8; n++) {
                *(float2*)(Y0 + n * 8) = make_float2(acc[m][n][0], acc[m][n][1]);
                *(float2*)(Y8 + n * 8) = make_float2(acc[m][n][2], acc[m][n][3]);
            }
        }
    }

    if (STATS) {
        float s1[2][2], s2[2][2];
#pragma unroll
        for (int m = 0; m < 2; m++) {
            float a0 = 0.f, q0 = 0.f, a1 = 0.f, q1 = 0.f;
#pragma unroll
            for (int n = 0; n < 8; n++) {
                a0 += acc[m][n][0]; q0 = fmaf(acc[m][n][0], acc[m][n][0], q0);
                a0 += acc[m][n][1]; q0 = fmaf(acc[m][n][1], acc[m][n][1], q0);
                a1 += acc[m][n][2]; q1 = fmaf(acc[m][n][2], acc[m][n][2], q1);
                a1 += acc[m][n][3]; q1 = fmaf(acc[m][n][3], acc[m][n][3], q1);
            }
            s1[m][0] = a0; s2[m][0] = q0; s1[m][1] = a1; s2[m][1] = q1;
        }
#pragma unroll
        for (int m = 0; m < 2; m++)
#pragma unroll
            for (int h = 0; h < 2; h++) {
#pragma unroll
                for (int off = 1; off <= 2; off <<= 1) {
                    s1[m][h] += __shfl_xor_sync(0xffffffffu, s1[m][h], off);
                    s2[m][h] += __shfl_xor_sync(0xffffffffu, s2[m][h], off);
                }
            }
        float* sb1 = (float*)SH;
        float* sb2 = sb1 + 256;
        __syncthreads();
        if (tig == 0) {
#pragma unroll
            for (int m = 0; m < 2; m++)
#pragma unroll
                for (int h = 0; h < 2; h++) {
                    int ol = wo * 32 + m * 16 + h * 8 + gid;
                    sb1[wn * 128 + ol] = s1[m][h];
                    sb2[wn * 128 + ol] = s2[m][h];
                }
        }
        __syncthreads();
        if (t < 128) {
            float tot = sb1[t] + sb1[128 + t];
            part[(((size_t)b * MTOT + ob0 + t) * nbx + bx) * 2 + 0] = tot;
        } else {
            int o = t - 128;
            float tot = sb2[o] + sb2[128 + o];
            part[(((size_t)b * MTOT + ob0 + o) * nbx + bx) * 2 + 1] = tot;
        }
    }
}

// ---------------------------------------------------------------------------
// Standalone GEMM kernel (K3, K5)
// ---------------------------------------------------------------------------
template <int KDIM, bool GATHER, bool BN, bool STATS, bool TRANSOUT, int MTOT>
__global__ void __launch_bounds__(256, 2) gemm_kernel(
    int wfbase,
    const float* __restrict__ X, int N,
    const float* __restrict__ P,
    const int*   __restrict__ idx,
    const float* __restrict__ bsc,
    const float* __restrict__ bbi,
    float* __restrict__ Y,
    float* __restrict__ part)
{
    __shared__ __align__(16) uint32_t SH[16384];
    __shared__ int idbuf[128];
    gemm_body<KDIM, GATHER, BN, STATS, TRANSOUT, MTOT>(
        SH, idbuf, blockIdx.z, blockIdx.y * 128, blockIdx.x * 128,
        blockIdx.y, gridDim.x, blockIdx.x,
        wfbase, X, N, P, idx, bsc, bbi, Y, part);
}

// ---------------------------------------------------------------------------
// FUSED kernel: bids [0,512) = pruned 1-NN (256 queries/CTA, thread-per-query)
//               bids [512,1024) = K2 (P_t = (w1a @ kf)^T) with preconverted W.
// NN CTAs dispatch first; K2 CTAs co-reside and fill idle slots.
// ---------------------------------------------------------------------------
__global__ void __launch_bounds__(256, 2) fused_nn_k2_kernel(
    const float* __restrict__ kf,
    float* __restrict__ P)
{
    __shared__ __align__(16) uint32_t SH[16384];
    __shared__ int idbuf[128];
    const int bid = blockIdx.x;
    if (bid < 512) {
        nn_body(bid * 256 + threadIdx.x);
    } else {
        const int g  = bid - 512;        // 0..511
        const int bx = g & 127;          // m-tile
        const int oy = (g >> 7) & 1;     // o-tile
        const int b  = g >> 8;           // batch
        gemm_body<C2_, false, false, false, true, H1_>(
            SH, idbuf, b, oy * 128, bx * 128, oy, 128, bx,
            WF_K2, kf, M_, nullptr, nullptr, nullptr, nullptr,
            P, nullptr);
    }
}

// ---------------------------------------------------------------------------
// Finalize BN stats: one block per channel
// ---------------------------------------------------------------------------
template <int MTOT>
__global__ void __launch_bounds__(128) fin_kernel(
    const float* __restrict__ part,
    const float* __restrict__ gamma, const float* __restrict__ beta,
    float* __restrict__ sc, float* __restrict__ bi, float invN)
{
    const int o = blockIdx.x;
    const int t = threadIdx.x;
    float s1 = 0.f, s2 = 0.f;
    for (int b = 0; b < B_; b++) {
        const float* p = part + ((size_t)b * MTOT + o) * NT_ * 2;
        for (int q = t; q < NT_; q += 128) {
            s1 += p[q * 2 + 0];
            s2 += p[q * 2 + 1];
        }
    }
#pragma unroll
    for (int off = 16; off; off >>= 1) {
        s1 += __shfl_down_sync(0xffffffffu, s1, off);
        s2 += __shfl_down_sync(0xffffffffu, s2, off);
    }
    __shared__ float r1[4], r2[4];
    if ((t & 31) == 0) { r1[t >> 5] = s1; r2[t >> 5] = s2; }
    __syncthreads();
    if (t == 0) {
        s1 = r1[0] + r1[1] + r1[2] + r1[3];
        s2 = r2[0] + r2[1] + r2[2] + r2[3];
        float mean = s1 * invN;
        float var  = s2 * invN - mean * mean;
        float rstd = rsqrtf(var + EPS_);
        float s    = gamma[o] * rstd;
        sc[o] = s;
        bi[o] = beta[o] - mean * s;
    }
}

// ---------------------------------------------------------------------------
// Final elementwise BN+ReLU in-place on d_out
// ---------------------------------------------------------------------------
__global__ void __launch_bounds__(256) bnfin_kernel(
    float* __restrict__ Y, const float* __restrict__ sc, const float* __restrict__ bi)
{
    int row = blockIdx.y;
    int ch  = row & (H2_ - 1);
    size_t base = (size_t)row * N_;
    int i = (blockIdx.x * 256 + threadIdx.x) * 4;
    float4 v = *(float4*)(Y + base + i);
    float s = sc[ch], b = bi[ch];
    v.x = fmaxf(fmaf(v.x, s, b), 0.f);
    v.y = fmaxf(fmaf(v.y, s, b), 0.f);
    v.z = fmaxf(fmaf(v.z, s, b), 0.f);
    v.w = fmaxf(fmaf(v.w, s, b), 0.f);
    *(float4*)(Y + base + i) = v;
}

// ---------------------------------------------------------------------------
// Launch
// ---------------------------------------------------------------------------
extern "C" void kernel_launch(void* const* d_in, const int* in_sizes, int n_in,
                              void* d_out, int out_size)
{
    const float* unknown = (const float*)d_in[0];
    const float* known   = (const float*)d_in[1];
    const float* uf      = (const float*)d_in[2];
    const float* kf      = (const float*)d_in[3];
    const float* w1      = (const float*)d_in[4];
    const float* gamma1  = (const float*)d_in[5];
    const float* beta1   = (const float*)d_in[6];
    const float* w2      = (const float*)d_in[7];
    const float* gamma2  = (const float*)d_in[8];
    const float* beta2   = (const float*)d_in[9];
    float* out = (float*)d_out;

    float *pP, *ph, *pp1, *pp2, *ps1, *pb1, *ps2, *pb2;
    int* pidx;
    cudaGetSymbolAddress((void**)&pP,   g_P);
    cudaGetSymbolAddress((void**)&ph,   g_h);
    cudaGetSymbolAddress((void**)&pp1,  g_part1);
    cudaGetSymbolAddress((void**)&pp2,  g_part2);
    cudaGetSymbolAddress((void**)&ps1,  g_scale1);
    cudaGetSymbolAddress((void**)&pb1,  g_bias1);
    cudaGetSymbolAddress((void**)&ps2,  g_scale2);
    cudaGetSymbolAddress((void**)&pb2,  g_bias2);
    cudaGetSymbolAddress((void**)&pidx, g_idx);

    const float invN = 1.0f / (float)(B_ * N_);

    // W fragment pre-conversion
    prep_w_kernel<<<(2 * 8 * 4096) / 256, 256>>>(w1, 384, 0,   8, 2, WF_K2);
    prep_w_kernel<<<(2 * 4 * 4096) / 256, 256>>>(w1, 384, 256, 4, 2, WF_K3);
    prep_w_kernel<<<(1 * 8 * 4096) / 256, 256>>>(w2, 256, 0,   8, 1, WF_K5);

    // grid binning for pruned 1-NN (32^3)
    zero_kernel<<<256, 256>>>();
    hist_kernel<<<(B_ * (M_ + N_)) / 256, 256>>>(unknown, known);
    scan_kernel<<<4, 1024>>>();
    scatter_kernel<<<(B_ * (M_ + N_)) / 256, 256>>>(unknown, known);

    // 1-NN (bids 0..511) + K2 (bids 512..1023) in one launch
    fused_nn_k2_kernel<<<1024, 256>>>(kf, pP);

    // K3: h = w1[:, 256:] @ uf + gather(P_t, idx); stats1
    gemm_kernel<C1_, true, false, true, false, H1_>
        <<<dim3(N_ / 128, H1_ / 128, B_), 256>>>(
            WF_K3, uf, N_, pP, pidx, nullptr, nullptr, ph, pp1);

    fin_kernel<H1_><<<H1_, 128>>>(pp1, gamma1, beta1, ps1, pb1, invN);

    // K5: out_pre = w2 @ relu(bn1(h)); stats2
    gemm_kernel<H1_, false, true, true, false, H2_>
        <<<dim3(N_ / 128, H2_ / 128, B_), 256>>>(
            WF_K5, ph, N_, nullptr, nullptr, ps1, pb1, out, pp2);

    fin_kernel<H2_><<<H2_, 128>>>(pp2, gamma2, beta2, ps2, pb2, invN);

    bnfin_kernel<<<dim3(N_ / 1024, B_ * H2_), 256>>>(out, ps2, pb2);
}